// round 12
// baseline (speedup 1.0000x reference)
#include <cuda_runtime.h>
#include <cuda_bf16.h>
#include <math.h>
#include <stdint.h>

// Problem dims
#define Lc 8
#define Dc 1024
#define Hc 16
#define FFc 4096
#define Tc 2048
#define Bc 2
#define HDc 64
#define Mc (Bc*Tc)   // 4096 tokens

// ---------------- scratch (device globals) ----------------
__device__ __nv_bfloat16 g_xH[(size_t)Mc*Dc];     // residual stream hi/lo (no fp32 master)
__device__ __nv_bfloat16 g_xL[(size_t)Mc*Dc];
__device__ __nv_bfloat16 g_aH[(size_t)Mc*FFc];
__device__ __nv_bfloat16 g_aL[(size_t)Mc*FFc];
__device__ __nv_bfloat16 g_qkvH[(size_t)Mc*3*Dc];   // q,k normalized; v scaled
__device__ __nv_bfloat16 g_qkvL[(size_t)Mc*3*Dc];
__device__ __nv_bfloat16 g_wqkvH[(size_t)Lc*3*Dc*Dc];
__device__ __nv_bfloat16 g_wqkvL[(size_t)Lc*3*Dc*Dc];
__device__ __nv_bfloat16 g_projH[(size_t)Lc*Dc*Dc];
__device__ __nv_bfloat16 g_projL[(size_t)Lc*Dc*Dc];
__device__ __nv_bfloat16 g_fcH[(size_t)Lc*FFc*Dc];
__device__ __nv_bfloat16 g_fcL[(size_t)Lc*FFc*Dc];
__device__ __nv_bfloat16 g_mlpH[(size_t)Lc*Dc*FFc];
__device__ __nv_bfloat16 g_mlpL[(size_t)Lc*Dc*FFc];

__device__ __forceinline__ float gelu_exact(float v){
    return 0.5f*v*(1.0f + erff(v*0.70710678118654752f));
}

// ---------------- PTX helpers ----------------
__device__ __forceinline__ uint32_t smem_u32(const void* p){
    uint32_t a;
    asm("{ .reg .u64 t; cvta.to.shared.u64 t, %1; cvt.u32.u64 %0, t; }" : "=r"(a) : "l"(p));
    return a;
}
#define CP_COMMIT()  asm volatile("cp.async.commit_group;" ::: "memory")
#define CP_WAIT1()   asm volatile("cp.async.wait_group 1;" ::: "memory")
#define CP_WAIT2()   asm volatile("cp.async.wait_group 2;" ::: "memory")
#define CP_WAIT0()   asm volatile("cp.async.wait_group 0;" ::: "memory")

__device__ __forceinline__ void cpasync16(uint32_t dst, const void* src){
    asm volatile("cp.async.cg.shared.global [%0], [%1], 16;" :: "r"(dst), "l"(src));
}
__device__ __forceinline__ void ldsm4(uint32_t addr, uint32_t& r0, uint32_t& r1, uint32_t& r2, uint32_t& r3){
    asm volatile("ldmatrix.sync.aligned.m8n8.x4.shared.b16 {%0,%1,%2,%3}, [%4];"
        : "=r"(r0), "=r"(r1), "=r"(r2), "=r"(r3) : "r"(addr));
}
__device__ __forceinline__ void ldsm4t(uint32_t addr, uint32_t& r0, uint32_t& r1, uint32_t& r2, uint32_t& r3){
    asm volatile("ldmatrix.sync.aligned.m8n8.x4.trans.shared.b16 {%0,%1,%2,%3}, [%4];"
        : "=r"(r0), "=r"(r1), "=r"(r2), "=r"(r3) : "r"(addr));
}
__device__ __forceinline__ void mma16816(float* c, const uint32_t* a, const uint32_t* b){
    asm volatile("mma.sync.aligned.m16n8k16.row.col.f32.bf16.bf16.f32 "
        "{%0,%1,%2,%3}, {%4,%5,%6,%7}, {%8,%9}, {%0,%1,%2,%3};"
        : "+f"(c[0]), "+f"(c[1]), "+f"(c[2]), "+f"(c[3])
        : "r"(a[0]), "r"(a[1]), "r"(a[2]), "r"(a[3]), "r"(b[0]), "r"(b[1]));
}

// ---------------- split helpers ----------------
__device__ __forceinline__ void split4(float4 v, __nv_bfloat16* hi, __nv_bfloat16* lo, size_t e){
    __nv_bfloat16 h0=__float2bfloat16(v.x), h1=__float2bfloat16(v.y);
    __nv_bfloat16 h2=__float2bfloat16(v.z), h3=__float2bfloat16(v.w);
    __nv_bfloat16 l0=__float2bfloat16(v.x-__bfloat162float(h0));
    __nv_bfloat16 l1=__float2bfloat16(v.y-__bfloat162float(h1));
    __nv_bfloat16 l2=__float2bfloat16(v.z-__bfloat162float(h2));
    __nv_bfloat16 l3=__float2bfloat16(v.w-__bfloat162float(h3));
    __nv_bfloat162 hp0; hp0.x=h0; hp0.y=h1;
    __nv_bfloat162 hp1; hp1.x=h2; hp1.y=h3;
    __nv_bfloat162 lp0; lp0.x=l0; lp0.y=l1;
    __nv_bfloat162 lp1; lp1.x=l2; lp1.y=l3;
    ((__nv_bfloat162*)hi)[e/2]   = hp0;
    ((__nv_bfloat162*)hi)[e/2+1] = hp1;
    ((__nv_bfloat162*)lo)[e/2]   = lp0;
    ((__nv_bfloat162*)lo)[e/2+1] = lp1;
}
__device__ __forceinline__ void split2(float x, float y, __nv_bfloat16* hi, __nv_bfloat16* lo, size_t e){
    __nv_bfloat16 h0=__float2bfloat16(x), h1=__float2bfloat16(y);
    __nv_bfloat16 l0=__float2bfloat16(x-__bfloat162float(h0));
    __nv_bfloat16 l1=__float2bfloat16(y-__bfloat162float(h1));
    __nv_bfloat162 hp; hp.x=h0; hp.y=h1;
    __nv_bfloat162 lp; lp.x=l0; lp.y=l1;
    ((__nv_bfloat162*)hi)[e/2] = hp;
    ((__nv_bfloat162*)lo)[e/2] = lp;
}
__device__ __forceinline__ void packsplit(float x, float y, uint32_t& h, uint32_t& l){
    __nv_bfloat16 hx=__float2bfloat16(x), hy=__float2bfloat16(y);
    __nv_bfloat16 lx=__float2bfloat16(x-__bfloat162float(hx));
    __nv_bfloat16 ly=__float2bfloat16(y-__bfloat162float(hy));
    __nv_bfloat162 hp; hp.x=hx; hp.y=hy;
    __nv_bfloat162 lp; lp.x=lx; lp.y=ly;
    h = *(uint32_t*)&hp; l = *(uint32_t*)&lp;
}

__global__ void split_kernel(const float* __restrict__ s, __nv_bfloat16* __restrict__ hi,
                             __nv_bfloat16* __restrict__ lo, int n4){
    int i = blockIdx.x*blockDim.x + threadIdx.x;
    if (i < n4){
        float4 v = ((const float4*)s)[i];
        split4(v, hi, lo, (size_t)i*4);
    }
}

// ---------------- pos add: planes only ----------------
__global__ void posadd_kernel(const float* __restrict__ q, const float* __restrict__ pos){
    int idx = blockIdx.x*blockDim.x + threadIdx.x;
    const int n4 = Mc*Dc/4;
    if (idx < n4){
        float4 a = ((const float4*)q)[idx];
        int pidx = idx % (Tc*Dc/4);
        float4 p = ((const float4*)pos)[pidx];
        a.x+=p.x; a.y+=p.y; a.z+=p.z; a.w+=p.w;
        split4(a, g_xH, g_xL, (size_t)idx*4);
    }
}

// ---------------- HMMA GEMM (round-8 core; residual via hi/lo planes) --------
enum { EPI_QKV=0, EPI_ADD=1, EPI_GELU=2 };

#define PLANE 8192                 // 128 rows x 64B (swizzled)
#define STG   (4*PLANE)            // 32768
#define NSTAGE 3
#define GEMM_SMEM (NSTAGE*STG)     // 98304

__device__ __forceinline__ void load_stage(uint32_t sb,
    const __nv_bfloat16* __restrict__ pAh, const __nv_bfloat16* __restrict__ pAl,
    const __nv_bfloat16* __restrict__ pBh, const __nv_bfloat16* __restrict__ pBl,
    int K, int kb)
{
    const __nv_bfloat16* planes[4] = {pAh, pAl, pBh, pBl};
    const int tid = threadIdx.x;
    #pragma unroll
    for (int t=0; t<8; t++){
        int id = t*256 + tid;
        int plane = id >> 9;
        int rem = id & 511;
        int row = rem >> 2, c = rem & 3;
        uint32_t dst = sb + plane*PLANE + row*64 + 16*(c ^ ((row>>1)&3));
        cpasync16(dst, planes[plane] + (size_t)row*K + kb*32 + c*8);
    }
}

template<int EPI>
__global__ __launch_bounds__(256,2)
void gemm_mma(const __nv_bfloat16* __restrict__ Ah, const __nv_bfloat16* __restrict__ Al,
              const __nv_bfloat16* __restrict__ Bh, const __nv_bfloat16* __restrict__ Bl,
              const float* __restrict__ aux,
              const __nv_bfloat16* __restrict__ Rh, const __nv_bfloat16* __restrict__ Rl,
              __nv_bfloat16* __restrict__ Oh, __nv_bfloat16* __restrict__ Ol,
              int N, int K)
{
    extern __shared__ char smem[];
    const uint32_t sbase = smem_u32(smem);
    const int tid = threadIdx.x;
    const int wid = tid >> 5, lane = tid & 31;
    const int wm = wid >> 1, wn = wid & 1;
    const int bm = blockIdx.y*128, bn = blockIdx.x*128;
    const int KB = K >> 5;

    const __nv_bfloat16* pAh = Ah + (size_t)bm*K;
    const __nv_bfloat16* pAl = Al + (size_t)bm*K;
    const __nv_bfloat16* pBh = Bh + (size_t)bn*K;
    const __nv_bfloat16* pBl = Bl + (size_t)bn*K;

    float acc[2][8][4];
    #pragma unroll
    for (int i=0;i<2;i++)
        #pragma unroll
        for (int j=0;j<8;j++)
            #pragma unroll
            for (int k=0;k<4;k++) acc[i][j][k]=0.f;

    const uint32_t s_lane = (lane >> 1) & 3;
    const uint32_t rowA = (uint32_t)(wm*32 + (lane & 15));
    const uint32_t aoff0 = rowA*64 + 16u*(((0u) | (uint32_t)(lane>>4)) ^ s_lane);
    const uint32_t aoff1 = rowA*64 + 16u*(((2u) | (uint32_t)(lane>>4)) ^ s_lane);
    const uint32_t rowB = (uint32_t)(wn*64 + ((lane>>4)<<3) + (lane & 7));
    const uint32_t bbit = (uint32_t)((lane>>3) & 1);
    const uint32_t boff0 = rowB*64 + 16u*(((0u) | bbit) ^ s_lane);
    const uint32_t boff1 = rowB*64 + 16u*(((2u) | bbit) ^ s_lane);

    load_stage(sbase + 0*STG, pAh, pAl, pBh, pBl, K, 0);
    CP_COMMIT();
    load_stage(sbase + 1*STG, pAh, pAl, pBh, pBl, K, 1);
    CP_COMMIT();

    int cur = 0, nxt2 = 2;
    for (int kb=0; kb<KB; kb++){
        if (kb+1 < KB) CP_WAIT1(); else CP_WAIT0();
        __syncthreads();
        if (kb+2 < KB){
            load_stage(sbase + nxt2*STG, pAh, pAl, pBh, pBl, K, kb+2);
            CP_COMMIT();
        }

        const uint32_t sb = sbase + cur*STG;
        #pragma unroll
        for (int ks=0; ks<2; ks++){
            const uint32_t aoff = ks ? aoff1 : aoff0;
            const uint32_t boff = ks ? boff1 : boff0;
            uint32_t aH[2][4], aL[2][4];
            #pragma unroll
            for (int mt=0; mt<2; mt++){
                uint32_t ad = sb + aoff + (uint32_t)mt*1024;
                ldsm4(ad, aH[mt][0], aH[mt][1], aH[mt][2], aH[mt][3]);
                ldsm4(ad + PLANE, aL[mt][0], aL[mt][1], aL[mt][2], aL[mt][3]);
            }
            #pragma unroll
            for (int nh=0; nh<2; nh++){
                uint32_t bH[4][2], bL[4][2];
                #pragma unroll
                for (int np=0; np<2; np++){
                    int ntp = nh*2 + np;
                    uint32_t bd = sb + 2*PLANE + boff + (uint32_t)ntp*1024;
                    ldsm4(bd, bH[2*np][0], bH[2*np][1], bH[2*np+1][0], bH[2*np+1][1]);
                    ldsm4(bd + PLANE, bL[2*np][0], bL[2*np][1], bL[2*np+1][0], bL[2*np+1][1]);
                }
                #pragma unroll
                for (int mt=0; mt<2; mt++)
                    #pragma unroll
                    for (int nt=0; nt<4; nt++)
                        mma16816(acc[mt][nh*4+nt], aH[mt], bH[nt]);
                #pragma unroll
                for (int mt=0; mt<2; mt++)
                    #pragma unroll
                    for (int nt=0; nt<4; nt++)
                        mma16816(acc[mt][nh*4+nt], aH[mt], bL[nt]);
                #pragma unroll
                for (int mt=0; mt<2; mt++)
                    #pragma unroll
                    for (int nt=0; nt<4; nt++)
                        mma16816(acc[mt][nh*4+nt], aL[mt], bH[nt]);
            }
        }
        cur = (cur == 2) ? 0 : cur+1;
        nxt2 = (nxt2 == 2) ? 0 : nxt2+1;
    }

    const int rbase = bm + wm*32 + (lane>>2);
    const int cbase = bn + wn*64 + (lane&3)*2;

    if (EPI == EPI_QKV){
        const bool isqk = (bn < 2*Dc);
        #pragma unroll
        for (int mt=0; mt<2; mt++){
            #pragma unroll
            for (int half=0; half<2; half++){
                const int row = rbase + mt*16 + half*8;
                float vx[8], vy[8];
                float ss = 0.f;
                #pragma unroll
                for (int nt=0; nt<8; nt++){
                    const int col = cbase + nt*8;
                    float2 sc = *(const float2*)&aux[col];
                    float x = acc[mt][nt][half*2+0]*sc.x;
                    float y = acc[mt][nt][half*2+1]*sc.y;
                    vx[nt] = x; vy[nt] = y;
                    ss += x*x + y*y;
                }
                if (isqk){
                    ss += __shfl_xor_sync(0xffffffffu, ss, 1);
                    ss += __shfl_xor_sync(0xffffffffu, ss, 2);
                    float inv = 1.f / fmaxf(sqrtf(ss), 1e-5f);
                    #pragma unroll
                    for (int nt=0; nt<8; nt++){ vx[nt]*=inv; vy[nt]*=inv; }
                }
                #pragma unroll
                for (int nt=0; nt<8; nt++){
                    const int col = cbase + nt*8;
                    split2(vx[nt], vy[nt], Oh, Ol, (size_t)row*N + col);
                }
            }
        }
    } else {
        #pragma unroll
        for (int mt=0; mt<2; mt++){
            #pragma unroll
            for (int nt=0; nt<8; nt++){
                const int col = cbase + nt*8;
                #pragma unroll
                for (int half=0; half<2; half++){
                    const int row = rbase + mt*16 + half*8;
                    float vxx = acc[mt][nt][half*2+0];
                    float vyy = acc[mt][nt][half*2+1];
                    if (EPI == EPI_ADD){
                        const size_t e = (size_t)row*N + col;
                        __nv_bfloat162 rh = *(const __nv_bfloat162*)&Rh[e];
                        __nv_bfloat162 rl = *(const __nv_bfloat162*)&Rl[e];
                        vxx += __bfloat162float(rh.x) + __bfloat162float(rl.x);
                        vyy += __bfloat162float(rh.y) + __bfloat162float(rl.y);
                        split2(vxx, vyy, Oh, Ol, e);
                    } else {
                        vxx = gelu_exact(vxx); vyy = gelu_exact(vyy);
                        split2(vxx, vyy, Oh, Ol, (size_t)row*N + col);
                    }
                }
            }
        }
    }
}

// ---------------- HMMA flash attention (round-11 winner, unchanged) ----------
#define APL 8192                   // 64 rows x 128B swizzled
#define ASTG (3*APL)               // 24576  (Kh, Vh, Vl)
#define NATT 4
#define ATT_SMEM (NATT*ASTG)       // 98304

__device__ __forceinline__ void attn_load(uint32_t s0, int b, int h, int kbase){
    const int tid = threadIdx.x;
    #pragma unroll
    for (int t=0; t<6; t++){
        int id = t*256 + tid;          // 0..1535
        int plane = id >> 9;
        int rem = id & 511;
        int row = rem >> 3, c = rem & 7;
        uint32_t dst = s0 + plane*APL + row*128 + 16*(c ^ (row & 7));
        const __nv_bfloat16* src;
        if (plane == 0)      src = g_qkvH + (size_t)(b*Tc + kbase + row)*(3*Dc) + Dc   + h*HDc + c*8;
        else if (plane == 1) src = g_qkvH + (size_t)(b*Tc + kbase + row)*(3*Dc) + 2*Dc + h*HDc + c*8;
        else                 src = g_qkvL + (size_t)(b*Tc + kbase + row)*(3*Dc) + 2*Dc + h*HDc + c*8;
        cpasync16(dst, src);
    }
}

__global__ __launch_bounds__(256)
void attn_mma(){
    extern __shared__ char smc[];
    const uint32_t sb = smem_u32(smc);
    const int tid = threadIdx.x;
    const int wid = tid >> 5, lane = tid & 31;
    const int qt = (int)gridDim.x - 1 - (int)blockIdx.x;
    const int bh = blockIdx.y, b = bh >> 4, h = bh & 15;
    const int qbase = qt*128;
    const int wrow = qbase + wid*16;
    const int cq = (lane & 3)*2;
    const int r1g = wrow + (lane >> 2), r2g = r1g + 8;

    uint32_t aQh[4][4], aQl[4][4];
    {
        const size_t rb1 = (size_t)(b*Tc + r1g)*(3*Dc) + h*HDc;
        const size_t rb2 = (size_t)(b*Tc + r2g)*(3*Dc) + h*HDc;
        #pragma unroll
        for (int c=0;c<4;c++){
            int col = 16*c + cq;
            aQh[c][0] = *(const uint32_t*)&g_qkvH[rb1 + col];
            aQh[c][1] = *(const uint32_t*)&g_qkvH[rb2 + col];
            aQh[c][2] = *(const uint32_t*)&g_qkvH[rb1 + col + 8];
            aQh[c][3] = *(const uint32_t*)&g_qkvH[rb2 + col + 8];
            aQl[c][0] = *(const uint32_t*)&g_qkvL[rb1 + col];
            aQl[c][1] = *(const uint32_t*)&g_qkvL[rb2 + col];
            aQl[c][2] = *(const uint32_t*)&g_qkvL[rb1 + col + 8];
            aQl[c][3] = *(const uint32_t*)&g_qkvL[rb2 + col + 8];
        }
    }

    float O[8][4];
    #pragma unroll
    for (int j=0;j<8;j++){ O[j][0]=0.f; O[j][1]=0.f; O[j][2]=0.f; O[j][3]=0.f; }
    float m1=-1e30f, m2=-1e30f, l1=0.f, l2=0.f;

    const uint32_t brow = (uint32_t)(((lane>>4)<<3) + (lane & 7));
    const uint32_t bbit = (uint32_t)((lane>>3) & 1);
    const uint32_t bsw  = (uint32_t)(lane & 7);
    const uint32_t vrow_l = (uint32_t)((lane & 7) + (((lane>>3)&1) << 3));
    const uint32_t vchk_l = (uint32_t)(lane >> 4);
    const int nkt = 2*qt + 2;

    attn_load(sb + 0*ASTG, b, h, 0);
    CP_COMMIT();
    attn_load(sb + 1*ASTG, b, h, 64);
    CP_COMMIT();
    if (nkt > 2) attn_load(sb + 2*ASTG, b, h, 128);
    CP_COMMIT();

    for (int kt=0; kt<nkt; kt++){
        CP_WAIT2();
        __syncthreads();
        if (kt+3 < nkt)
            attn_load(sb + ((kt+3)&3)*ASTG, b, h, (kt+3)*64);
        CP_COMMIT();

        const uint32_t st = sb + (kt&3)*ASTG;
        const int kbase = kt*64;

        float S[8][4];
        #pragma unroll
        for (int j=0;j<8;j++){ S[j][0]=0.f; S[j][1]=0.f; S[j][2]=0.f; S[j][3]=0.f; }
        #pragma unroll
        for (int c=0;c<4;c++){
            const uint32_t coff = 16u*(((uint32_t)(2*c) | bbit) ^ bsw);
            uint32_t bKh[8][2];
            #pragma unroll
            for (int ntp=0; ntp<4; ntp++){
                uint32_t ad = st + (brow + (uint32_t)ntp*16)*128 + coff;
                ldsm4(ad, bKh[2*ntp][0], bKh[2*ntp][1], bKh[2*ntp+1][0], bKh[2*ntp+1][1]);
            }
            #pragma unroll
            for (int j=0;j<8;j++) mma16816(S[j], aQh[c], bKh[j]);
            #pragma unroll
            for (int j=0;j<8;j++) mma16816(S[j], aQl[c], bKh[j]);
        }

        const bool need_mask = (kt >= 2*qt);
        #pragma unroll
        for (int j=0;j<8;j++){
            int col0 = kbase + j*8 + cq;
            #pragma unroll
            for (int e=0;e<4;e++){
                float v = S[j][e]*0.125f;
                if (need_mask){
                    int col = col0 + (e & 1);
                    int row = (e < 2) ? r1g : r2g;
                    if (col > row) v = -1e30f;
                }
                S[j][e] = v;
            }
        }

        float mx1=-1e30f, mx2=-1e30f;
        #pragma unroll
        for (int j=0;j<8;j++){
            mx1 = fmaxf(mx1, fmaxf(S[j][0], S[j][1]));
            mx2 = fmaxf(mx2, fmaxf(S[j][2], S[j][3]));
        }
        #pragma unroll
        for (int o=1;o<4;o<<=1){
            mx1 = fmaxf(mx1, __shfl_xor_sync(0xffffffffu, mx1, o));
            mx2 = fmaxf(mx2, __shfl_xor_sync(0xffffffffu, mx2, o));
        }
        float mn1 = fmaxf(m1, mx1), mn2 = fmaxf(m2, mx2);
        float co1 = __expf(m1 - mn1), co2 = __expf(m2 - mn2);
        float rs1 = 0.f, rs2 = 0.f;
        #pragma unroll
        for (int j=0;j<8;j++){
            S[j][0] = __expf(S[j][0]-mn1); S[j][1] = __expf(S[j][1]-mn1);
            S[j][2] = __expf(S[j][2]-mn2); S[j][3] = __expf(S[j][3]-mn2);
            rs1 += S[j][0] + S[j][1];
            rs2 += S[j][2] + S[j][3];
        }
        #pragma unroll
        for (int o=1;o<4;o<<=1){
            rs1 += __shfl_xor_sync(0xffffffffu, rs1, o);
            rs2 += __shfl_xor_sync(0xffffffffu, rs2, o);
        }
        l1 = l1*co1 + rs1;  m1 = mn1;
        l2 = l2*co2 + rs2;  m2 = mn2;
        #pragma unroll
        for (int j=0;j<8;j++){
            O[j][0]*=co1; O[j][1]*=co1; O[j][2]*=co2; O[j][3]*=co2;
        }

        uint32_t pH[4][4], pL[4][4];
        #pragma unroll
        for (int c=0;c<4;c++){
            packsplit(S[2*c][0],   S[2*c][1],   pH[c][0], pL[c][0]);
            packsplit(S[2*c][2],   S[2*c][3],   pH[c][1], pL[c][1]);
            packsplit(S[2*c+1][0], S[2*c+1][1], pH[c][2], pL[c][2]);
            packsplit(S[2*c+1][2], S[2*c+1][3], pH[c][3], pL[c][3]);
        }

        #pragma unroll
        for (int c=0;c<4;c++){
            const uint32_t vrow = (uint32_t)(c*16) + vrow_l;
            uint32_t bVh[8][2], bVl[8][2];
            #pragma unroll
            for (int ntp=0; ntp<4; ntp++){
                uint32_t chunk = ((uint32_t)(2*ntp) + vchk_l) ^ (vrow & 7);
                uint32_t ad = st + APL + vrow*128 + 16u*chunk;
                ldsm4t(ad,        bVh[2*ntp][0], bVh[2*ntp][1], bVh[2*ntp+1][0], bVh[2*ntp+1][1]);
                ldsm4t(ad + APL,  bVl[2*ntp][0], bVl[2*ntp][1], bVl[2*ntp+1][0], bVl[2*ntp+1][1]);
            }
            #pragma unroll
            for (int j=0;j<8;j++) mma16816(O[j], pH[c], bVh[j]);
            #pragma unroll
            for (int j=0;j<8;j++) mma16816(O[j], pH[c], bVl[j]);
            #pragma unroll
            for (int j=0;j<8;j++) mma16816(O[j], pL[c], bVh[j]);
        }
    }

    const float i1 = 1.f/l1, i2 = 1.f/l2;
    const size_t ob1 = (size_t)(b*Tc + r1g)*Dc + h*HDc;
    const size_t ob2 = (size_t)(b*Tc + r2g)*Dc + h*HDc;
    #pragma unroll
    for (int j=0;j<8;j++){
        int col = j*8 + cq;
        split2(O[j][0]*i1, O[j][1]*i1, g_aH, g_aL, ob1 + col);
        split2(O[j][2]*i2, O[j][3]*i2, g_aH, g_aL, ob2 + col);
    }
}

// ---------------- final LayerNorm (reads residual planes) ----------------
__global__ void ln_kernel(const float* __restrict__ gamma, float* __restrict__ out){
    const int row = blockIdx.x, t = threadIdx.x;
    const size_t base = (size_t)row*Dc + t*4;
    __nv_bfloat162 h0 = *(const __nv_bfloat162*)&g_xH[base];
    __nv_bfloat162 h1 = *(const __nv_bfloat162*)&g_xH[base+2];
    __nv_bfloat162 l0 = *(const __nv_bfloat162*)&g_xL[base];
    __nv_bfloat162 l1v = *(const __nv_bfloat162*)&g_xL[base+2];
    float4 xv;
    xv.x = __bfloat162float(h0.x) + __bfloat162float(l0.x);
    xv.y = __bfloat162float(h0.y) + __bfloat162float(l0.y);
    xv.z = __bfloat162float(h1.x) + __bfloat162float(l1v.x);
    xv.w = __bfloat162float(h1.y) + __bfloat162float(l1v.y);
    float s = xv.x+xv.y+xv.z+xv.w;
    __shared__ float red[16];
    #pragma unroll
    for (int o=16;o;o>>=1) s += __shfl_xor_sync(0xffffffffu, s, o);
    if ((t&31)==0) red[t>>5] = s;
    __syncthreads();
    float tot = 0.f;
    #pragma unroll
    for (int w=0;w<8;w++) tot += red[w];
    float mean = tot*(1.f/Dc);
    float dx=xv.x-mean, dy=xv.y-mean, dz=xv.z-mean, dw=xv.w-mean;
    float ss = dx*dx+dy*dy+dz*dz+dw*dw;
    #pragma unroll
    for (int o=16;o;o>>=1) ss += __shfl_xor_sync(0xffffffffu, ss, o);
    if ((t&31)==0) red[8+(t>>5)] = ss;
    __syncthreads();
    float tv = 0.f;
    #pragma unroll
    for (int w=0;w<8;w++) tv += red[8+w];
    float inv = rsqrtf(tv*(1.f/Dc) + 1e-5f);
    float4 g4 = ((const float4*)gamma)[t];
    float4 o4 = make_float4(dx*inv*g4.x, dy*inv*g4.y, dz*inv*g4.z, dw*inv*g4.w);
    ((float4*)out)[(size_t)row*(Dc/4) + t] = o4;
}

// ---------------- launch ----------------
extern "C" void kernel_launch(void* const* d_in, const int* in_sizes, int n_in,
                              void* d_out, int out_size)
{
    const float* q      = (const float*)d_in[0];
    const float* pos    = (const float*)d_in[1];
    const float* Wqkv   = (const float*)d_in[2];
    const float* convw  = (const float*)d_in[3];
    const float* projw  = (const float*)d_in[4];
    const float* fcw    = (const float*)d_in[5];
    const float* mlpw   = (const float*)d_in[6];
    const float* gamma  = (const float*)d_in[7];

    __nv_bfloat16 *xH,*xL,*aH,*aL,*qkvH,*qkvL,*wqkvH,*wqkvL,*projH,*projL,*fcH,*fcL,*mlpH,*mlpL;
    cudaGetSymbolAddress((void**)&xH, g_xH);   cudaGetSymbolAddress((void**)&xL, g_xL);
    cudaGetSymbolAddress((void**)&aH, g_aH);   cudaGetSymbolAddress((void**)&aL, g_aL);
    cudaGetSymbolAddress((void**)&qkvH, g_qkvH); cudaGetSymbolAddress((void**)&qkvL, g_qkvL);
    cudaGetSymbolAddress((void**)&wqkvH, g_wqkvH); cudaGetSymbolAddress((void**)&wqkvL, g_wqkvL);
    cudaGetSymbolAddress((void**)&projH, g_projH); cudaGetSymbolAddress((void**)&projL, g_projL);
    cudaGetSymbolAddress((void**)&fcH, g_fcH);     cudaGetSymbolAddress((void**)&fcL, g_fcL);
    cudaGetSymbolAddress((void**)&mlpH, g_mlpH);   cudaGetSymbolAddress((void**)&mlpL, g_mlpL);

    cudaFuncSetAttribute(attn_mma, cudaFuncAttributeMaxDynamicSharedMemorySize, ATT_SMEM);
    cudaFuncSetAttribute(gemm_mma<EPI_QKV>,  cudaFuncAttributeMaxDynamicSharedMemorySize, GEMM_SMEM);
    cudaFuncSetAttribute(gemm_mma<EPI_ADD>,  cudaFuncAttributeMaxDynamicSharedMemorySize, GEMM_SMEM);
    cudaFuncSetAttribute(gemm_mma<EPI_GELU>, cudaFuncAttributeMaxDynamicSharedMemorySize, GEMM_SMEM);

    // split weights
    {
        int n4;
        n4 = Lc*3*Dc*Dc/4; split_kernel<<<n4/256, 256>>>(Wqkv, wqkvH, wqkvL, n4);
        n4 = Lc*Dc*Dc/4;   split_kernel<<<n4/256, 256>>>(projw, projH, projL, n4);
        n4 = Lc*FFc*Dc/4;  split_kernel<<<n4/256, 256>>>(fcw, fcH, fcL, n4);
        n4 = Lc*Dc*FFc/4;  split_kernel<<<n4/256, 256>>>(mlpw, mlpH, mlpL, n4);
    }

    posadd_kernel<<<Mc*Dc/4/256, 256>>>(q, pos);

    for (int l=0; l<Lc; l++){
        gemm_mma<EPI_QKV><<<dim3(3*Dc/128, Mc/128), 256, GEMM_SMEM>>>(
            xH, xL, wqkvH + (size_t)l*3*Dc*Dc, wqkvL + (size_t)l*3*Dc*Dc,
            convw + (size_t)l*3*Dc, nullptr, nullptr, qkvH, qkvL, 3*Dc, Dc);
        attn_mma<<<dim3(Tc/128, Bc*Hc), 256, ATT_SMEM>>>();
        // proj: x = x + attn@proj^T  (residual + output via planes)
        gemm_mma<EPI_ADD><<<dim3(Dc/128, Mc/128), 256, GEMM_SMEM>>>(
            aH, aL, projH + (size_t)l*Dc*Dc, projL + (size_t)l*Dc*Dc,
            nullptr, xH, xL, xH, xL, Dc, Dc);
        gemm_mma<EPI_GELU><<<dim3(FFc/128, Mc/128), 256, GEMM_SMEM>>>(
            xH, xL, fcH + (size_t)l*FFc*Dc, fcL + (size_t)l*FFc*Dc,
            nullptr, nullptr, nullptr, aH, aL, FFc, Dc);
        gemm_mma<EPI_ADD><<<dim3(Dc/128, Mc/128), 256, GEMM_SMEM>>>(
            aH, aL, mlpH + (size_t)l*Dc*FFc, mlpL + (size_t)l*Dc*FFc,
            nullptr, xH, xL, xH, xL, Dc, FFc);
    }

    ln_kernel<<<Mc, 256>>>(gamma, (float*)d_out);
}

// round 13
// speedup vs baseline: 1.0458x; 1.0458x over previous
#include <cuda_runtime.h>
#include <cuda_bf16.h>
#include <math.h>
#include <stdint.h>

// Problem dims
#define Lc 8
#define Dc 1024
#define Hc 16
#define FFc 4096
#define Tc 2048
#define Bc 2
#define HDc 64
#define Mc (Bc*Tc)   // 4096 tokens

// ---------------- scratch (device globals) ----------------
__device__ float g_x[Mc*Dc];

__device__ __nv_bfloat16 g_xH[(size_t)Mc*Dc];
__device__ __nv_bfloat16 g_xL[(size_t)Mc*Dc];
__device__ __nv_bfloat16 g_aH[(size_t)Mc*FFc];
__device__ __nv_bfloat16 g_aL[(size_t)Mc*FFc];
__device__ __nv_bfloat16 g_qkvH[(size_t)Mc*3*Dc];   // q,k normalized; v scaled
__device__ __nv_bfloat16 g_qkvL[(size_t)Mc*3*Dc];
__device__ __nv_bfloat16 g_wqkvH[(size_t)Lc*3*Dc*Dc];
__device__ __nv_bfloat16 g_wqkvL[(size_t)Lc*3*Dc*Dc];
__device__ __nv_bfloat16 g_projH[(size_t)Lc*Dc*Dc];
__device__ __nv_bfloat16 g_projL[(size_t)Lc*Dc*Dc];
__device__ __nv_bfloat16 g_fcH[(size_t)Lc*FFc*Dc];
__device__ __nv_bfloat16 g_fcL[(size_t)Lc*FFc*Dc];
__device__ __nv_bfloat16 g_mlpH[(size_t)Lc*Dc*FFc];
__device__ __nv_bfloat16 g_mlpL[(size_t)Lc*Dc*FFc];

__device__ __forceinline__ float gelu_exact(float v){
    return 0.5f*v*(1.0f + erff(v*0.70710678118654752f));
}

// ---------------- PTX helpers ----------------
__device__ __forceinline__ uint32_t smem_u32(const void* p){
    uint32_t a;
    asm("{ .reg .u64 t; cvta.to.shared.u64 t, %1; cvt.u32.u64 %0, t; }" : "=r"(a) : "l"(p));
    return a;
}
#define CP_COMMIT()  asm volatile("cp.async.commit_group;" ::: "memory")
#define CP_WAIT1()   asm volatile("cp.async.wait_group 1;" ::: "memory")
#define CP_WAIT2()   asm volatile("cp.async.wait_group 2;" ::: "memory")
#define CP_WAIT0()   asm volatile("cp.async.wait_group 0;" ::: "memory")

__device__ __forceinline__ void cpasync16(uint32_t dst, const void* src){
    asm volatile("cp.async.cg.shared.global [%0], [%1], 16;" :: "r"(dst), "l"(src));
}
__device__ __forceinline__ void ldsm4(uint32_t addr, uint32_t& r0, uint32_t& r1, uint32_t& r2, uint32_t& r3){
    asm volatile("ldmatrix.sync.aligned.m8n8.x4.shared.b16 {%0,%1,%2,%3}, [%4];"
        : "=r"(r0), "=r"(r1), "=r"(r2), "=r"(r3) : "r"(addr));
}
__device__ __forceinline__ void ldsm4t(uint32_t addr, uint32_t& r0, uint32_t& r1, uint32_t& r2, uint32_t& r3){
    asm volatile("ldmatrix.sync.aligned.m8n8.x4.trans.shared.b16 {%0,%1,%2,%3}, [%4];"
        : "=r"(r0), "=r"(r1), "=r"(r2), "=r"(r3) : "r"(addr));
}
__device__ __forceinline__ void mma16816(float* c, const uint32_t* a, const uint32_t* b){
    asm volatile("mma.sync.aligned.m16n8k16.row.col.f32.bf16.bf16.f32 "
        "{%0,%1,%2,%3}, {%4,%5,%6,%7}, {%8,%9}, {%0,%1,%2,%3};"
        : "+f"(c[0]), "+f"(c[1]), "+f"(c[2]), "+f"(c[3])
        : "r"(a[0]), "r"(a[1]), "r"(a[2]), "r"(a[3]), "r"(b[0]), "r"(b[1]));
}

// ---------------- split helpers ----------------
__device__ __forceinline__ void split4(float4 v, __nv_bfloat16* hi, __nv_bfloat16* lo, size_t e){
    __nv_bfloat16 h0=__float2bfloat16(v.x), h1=__float2bfloat16(v.y);
    __nv_bfloat16 h2=__float2bfloat16(v.z), h3=__float2bfloat16(v.w);
    __nv_bfloat16 l0=__float2bfloat16(v.x-__bfloat162float(h0));
    __nv_bfloat16 l1=__float2bfloat16(v.y-__bfloat162float(h1));
    __nv_bfloat16 l2=__float2bfloat16(v.z-__bfloat162float(h2));
    __nv_bfloat16 l3=__float2bfloat16(v.w-__bfloat162float(h3));
    __nv_bfloat162 hp0; hp0.x=h0; hp0.y=h1;
    __nv_bfloat162 hp1; hp1.x=h2; hp1.y=h3;
    __nv_bfloat162 lp0; lp0.x=l0; lp0.y=l1;
    __nv_bfloat162 lp1; lp1.x=l2; lp1.y=l3;
    ((__nv_bfloat162*)hi)[e/2]   = hp0;
    ((__nv_bfloat162*)hi)[e/2+1] = hp1;
    ((__nv_bfloat162*)lo)[e/2]   = lp0;
    ((__nv_bfloat162*)lo)[e/2+1] = lp1;
}
__device__ __forceinline__ void split2(float x, float y, __nv_bfloat16* hi, __nv_bfloat16* lo, size_t e){
    __nv_bfloat16 h0=__float2bfloat16(x), h1=__float2bfloat16(y);
    __nv_bfloat16 l0=__float2bfloat16(x-__bfloat162float(h0));
    __nv_bfloat16 l1=__float2bfloat16(y-__bfloat162float(h1));
    __nv_bfloat162 hp; hp.x=h0; hp.y=h1;
    __nv_bfloat162 lp; lp.x=l0; lp.y=l1;
    ((__nv_bfloat162*)hi)[e/2] = hp;
    ((__nv_bfloat162*)lo)[e/2] = lp;
}
__device__ __forceinline__ void packsplit(float x, float y, uint32_t& h, uint32_t& l){
    __nv_bfloat16 hx=__float2bfloat16(x), hy=__float2bfloat16(y);
    __nv_bfloat16 lx=__float2bfloat16(x-__bfloat162float(hx));
    __nv_bfloat16 ly=__float2bfloat16(y-__bfloat162float(hy));
    __nv_bfloat162 hp; hp.x=hx; hp.y=hy;
    __nv_bfloat162 lp; lp.x=lx; lp.y=ly;
    h = *(uint32_t*)&hp; l = *(uint32_t*)&lp;
}

__global__ void split_kernel(const float* __restrict__ s, __nv_bfloat16* __restrict__ hi,
                             __nv_bfloat16* __restrict__ lo, int n4){
    int i = blockIdx.x*blockDim.x + threadIdx.x;
    if (i < n4){
        float4 v = ((const float4*)s)[i];
        split4(v, hi, lo, (size_t)i*4);
    }
}

// ---------------- pos add ----------------
__global__ void posadd_kernel(const float* __restrict__ q, const float* __restrict__ pos){
    int idx = blockIdx.x*blockDim.x + threadIdx.x;
    const int n4 = Mc*Dc/4;
    if (idx < n4){
        float4 a = ((const float4*)q)[idx];
        int pidx = idx % (Tc*Dc/4);
        float4 p = ((const float4*)pos)[pidx];
        a.x+=p.x; a.y+=p.y; a.z+=p.z; a.w+=p.w;
        ((float4*)g_x)[idx] = a;
        split4(a, g_xH, g_xL, (size_t)idx*4);
    }
}

// ---------------- HMMA GEMM (round-8 core; EPI_QKV fused scale+l2norm) --------
enum { EPI_QKV=0, EPI_ADD=1, EPI_GELU=2 };

#define PLANE 8192                 // 128 rows x 64B (swizzled)
#define STG   (4*PLANE)            // 32768
#define NSTAGE 3
#define GEMM_SMEM (NSTAGE*STG)     // 98304

__device__ __forceinline__ void load_stage(uint32_t sb,
    const __nv_bfloat16* __restrict__ pAh, const __nv_bfloat16* __restrict__ pAl,
    const __nv_bfloat16* __restrict__ pBh, const __nv_bfloat16* __restrict__ pBl,
    int K, int kb)
{
    const __nv_bfloat16* planes[4] = {pAh, pAl, pBh, pBl};
    const int tid = threadIdx.x;
    #pragma unroll
    for (int t=0; t<8; t++){
        int id = t*256 + tid;
        int plane = id >> 9;
        int rem = id & 511;
        int row = rem >> 2, c = rem & 3;
        uint32_t dst = sb + plane*PLANE + row*64 + 16*(c ^ ((row>>1)&3));
        cpasync16(dst, planes[plane] + (size_t)row*K + kb*32 + c*8);
    }
}

template<int EPI>
__global__ __launch_bounds__(256,2)
void gemm_mma(const __nv_bfloat16* __restrict__ Ah, const __nv_bfloat16* __restrict__ Al,
              const __nv_bfloat16* __restrict__ Bh, const __nv_bfloat16* __restrict__ Bl,
              const float* __restrict__ aux, float* __restrict__ C,
              __nv_bfloat16* __restrict__ Oh, __nv_bfloat16* __restrict__ Ol,
              int N, int K)
{
    extern __shared__ char smem[];
    const uint32_t sbase = smem_u32(smem);
    const int tid = threadIdx.x;
    const int wid = tid >> 5, lane = tid & 31;
    const int wm = wid >> 1, wn = wid & 1;
    const int bm = blockIdx.y*128, bn = blockIdx.x*128;
    const int KB = K >> 5;

    const __nv_bfloat16* pAh = Ah + (size_t)bm*K;
    const __nv_bfloat16* pAl = Al + (size_t)bm*K;
    const __nv_bfloat16* pBh = Bh + (size_t)bn*K;
    const __nv_bfloat16* pBl = Bl + (size_t)bn*K;

    float acc[2][8][4];
    #pragma unroll
    for (int i=0;i<2;i++)
        #pragma unroll
        for (int j=0;j<8;j++)
            #pragma unroll
            for (int k=0;k<4;k++) acc[i][j][k]=0.f;

    const uint32_t s_lane = (lane >> 1) & 3;
    const uint32_t rowA = (uint32_t)(wm*32 + (lane & 15));
    const uint32_t aoff0 = rowA*64 + 16u*(((0u) | (uint32_t)(lane>>4)) ^ s_lane);
    const uint32_t aoff1 = rowA*64 + 16u*(((2u) | (uint32_t)(lane>>4)) ^ s_lane);
    const uint32_t rowB = (uint32_t)(wn*64 + ((lane>>4)<<3) + (lane & 7));
    const uint32_t bbit = (uint32_t)((lane>>3) & 1);
    const uint32_t boff0 = rowB*64 + 16u*(((0u) | bbit) ^ s_lane);
    const uint32_t boff1 = rowB*64 + 16u*(((2u) | bbit) ^ s_lane);

    load_stage(sbase + 0*STG, pAh, pAl, pBh, pBl, K, 0);
    CP_COMMIT();
    load_stage(sbase + 1*STG, pAh, pAl, pBh, pBl, K, 1);
    CP_COMMIT();

    int cur = 0, nxt2 = 2;
    for (int kb=0; kb<KB; kb++){
        if (kb+1 < KB) CP_WAIT1(); else CP_WAIT0();
        __syncthreads();
        if (kb+2 < KB){
            load_stage(sbase + nxt2*STG, pAh, pAl, pBh, pBl, K, kb+2);
            CP_COMMIT();
        }

        const uint32_t sb = sbase + cur*STG;
        #pragma unroll
        for (int ks=0; ks<2; ks++){
            const uint32_t aoff = ks ? aoff1 : aoff0;
            const uint32_t boff = ks ? boff1 : boff0;
            uint32_t aH[2][4], aL[2][4];
            #pragma unroll
            for (int mt=0; mt<2; mt++){
                uint32_t ad = sb + aoff + (uint32_t)mt*1024;
                ldsm4(ad, aH[mt][0], aH[mt][1], aH[mt][2], aH[mt][3]);
                ldsm4(ad + PLANE, aL[mt][0], aL[mt][1], aL[mt][2], aL[mt][3]);
            }
            #pragma unroll
            for (int nh=0; nh<2; nh++){
                uint32_t bH[4][2], bL[4][2];
                #pragma unroll
                for (int np=0; np<2; np++){
                    int ntp = nh*2 + np;
                    uint32_t bd = sb + 2*PLANE + boff + (uint32_t)ntp*1024;
                    ldsm4(bd, bH[2*np][0], bH[2*np][1], bH[2*np+1][0], bH[2*np+1][1]);
                    ldsm4(bd + PLANE, bL[2*np][0], bL[2*np][1], bL[2*np+1][0], bL[2*np+1][1]);
                }
                #pragma unroll
                for (int mt=0; mt<2; mt++)
                    #pragma unroll
                    for (int nt=0; nt<4; nt++)
                        mma16816(acc[mt][nh*4+nt], aH[mt], bH[nt]);
                #pragma unroll
                for (int mt=0; mt<2; mt++)
                    #pragma unroll
                    for (int nt=0; nt<4; nt++)
                        mma16816(acc[mt][nh*4+nt], aH[mt], bL[nt]);
                #pragma unroll
                for (int mt=0; mt<2; mt++)
                    #pragma unroll
                    for (int nt=0; nt<4; nt++)
                        mma16816(acc[mt][nh*4+nt], aL[mt], bH[nt]);
            }
        }
        cur = (cur == 2) ? 0 : cur+1;
        nxt2 = (nxt2 == 2) ? 0 : nxt2+1;
    }

    const int rbase = bm + wm*32 + (lane>>2);
    const int cbase = bn + wn*64 + (lane&3)*2;

    if (EPI == EPI_QKV){
        const bool isqk = (bn < 2*Dc);
        #pragma unroll
        for (int mt=0; mt<2; mt++){
            #pragma unroll
            for (int half=0; half<2; half++){
                const int row = rbase + mt*16 + half*8;
                float vx[8], vy[8];
                float ss = 0.f;
                #pragma unroll
                for (int nt=0; nt<8; nt++){
                    const int col = cbase + nt*8;
                    float2 sc = *(const float2*)&aux[col];
                    float x = acc[mt][nt][half*2+0]*sc.x;
                    float y = acc[mt][nt][half*2+1]*sc.y;
                    vx[nt] = x; vy[nt] = y;
                    ss += x*x + y*y;
                }
                if (isqk){
                    ss += __shfl_xor_sync(0xffffffffu, ss, 1);
                    ss += __shfl_xor_sync(0xffffffffu, ss, 2);
                    float inv = 1.f / fmaxf(sqrtf(ss), 1e-5f);
                    #pragma unroll
                    for (int nt=0; nt<8; nt++){ vx[nt]*=inv; vy[nt]*=inv; }
                }
                #pragma unroll
                for (int nt=0; nt<8; nt++){
                    const int col = cbase + nt*8;
                    split2(vx[nt], vy[nt], Oh, Ol, (size_t)row*N + col);
                }
            }
        }
    } else {
        #pragma unroll
        for (int mt=0; mt<2; mt++){
            #pragma unroll
            for (int nt=0; nt<8; nt++){
                const int col = cbase + nt*8;
                #pragma unroll
                for (int half=0; half<2; half++){
                    const int row = rbase + mt*16 + half*8;
                    float vxx = acc[mt][nt][half*2+0];
                    float vyy = acc[mt][nt][half*2+1];
                    if (EPI == EPI_ADD){
                        float2 r = *(const float2*)&aux[(size_t)row*N + col];
                        vxx += r.x; vyy += r.y;
                        *(float2*)&C[(size_t)row*N + col] = make_float2(vxx, vyy);
                        split2(vxx, vyy, Oh, Ol, (size_t)row*N + col);
                    } else {
                        vxx = gelu_exact(vxx); vyy = gelu_exact(vyy);
                        split2(vxx, vyy, Oh, Ol, (size_t)row*N + col);
                    }
                }
            }
        }
    }
}

// ---------------- HMMA flash attention: BM=128, BN=64, SW128 swizzle,
//  K hi-plane + V hi-plane only; PV = (pH+pL).Vh; 4-stage cp.async -------------
#define APL 8192                   // 64 rows x 128B swizzled
#define ASTG (2*APL)               // 16384  (Kh, Vh)
#define NATT 4
#define ATT_SMEM (NATT*ASTG)       // 65536

__device__ __forceinline__ void attn_load(uint32_t s0, int b, int h, int kbase){
    const int tid = threadIdx.x;
    #pragma unroll
    for (int t=0; t<4; t++){
        int id = t*256 + tid;          // 0..1023
        int plane = id >> 9;           // 0=Kh, 1=Vh
        int rem = id & 511;
        int row = rem >> 3, c = rem & 7;
        uint32_t dst = s0 + plane*APL + row*128 + 16*(c ^ (row & 7));
        const __nv_bfloat16* src = g_qkvH + (size_t)(b*Tc + kbase + row)*(3*Dc)
                                 + ((plane == 0) ? Dc : 2*Dc) + h*HDc + c*8;
        cpasync16(dst, src);
    }
}

__global__ __launch_bounds__(256)
void attn_mma(){
    extern __shared__ char smc[];
    const uint32_t sb = smem_u32(smc);
    const int tid = threadIdx.x;
    const int wid = tid >> 5, lane = tid & 31;
    const int qt = (int)gridDim.x - 1 - (int)blockIdx.x;     // heavy CTAs first
    const int bh = blockIdx.y, b = bh >> 4, h = bh & 15;
    const int qbase = qt*128;
    const int wrow = qbase + wid*16;
    const int cq = (lane & 3)*2;
    const int r1g = wrow + (lane >> 2), r2g = r1g + 8;

    uint32_t aQh[4][4], aQl[4][4];
    {
        const size_t rb1 = (size_t)(b*Tc + r1g)*(3*Dc) + h*HDc;
        const size_t rb2 = (size_t)(b*Tc + r2g)*(3*Dc) + h*HDc;
        #pragma unroll
        for (int c=0;c<4;c++){
            int col = 16*c + cq;
            aQh[c][0] = *(const uint32_t*)&g_qkvH[rb1 + col];
            aQh[c][1] = *(const uint32_t*)&g_qkvH[rb2 + col];
            aQh[c][2] = *(const uint32_t*)&g_qkvH[rb1 + col + 8];
            aQh[c][3] = *(const uint32_t*)&g_qkvH[rb2 + col + 8];
            aQl[c][0] = *(const uint32_t*)&g_qkvL[rb1 + col];
            aQl[c][1] = *(const uint32_t*)&g_qkvL[rb2 + col];
            aQl[c][2] = *(const uint32_t*)&g_qkvL[rb1 + col + 8];
            aQl[c][3] = *(const uint32_t*)&g_qkvL[rb2 + col + 8];
        }
    }

    float O[8][4];
    #pragma unroll
    for (int j=0;j<8;j++){ O[j][0]=0.f; O[j][1]=0.f; O[j][2]=0.f; O[j][3]=0.f; }
    float m1=-1e30f, m2=-1e30f, l1=0.f, l2=0.f;

    const uint32_t brow = (uint32_t)(((lane>>4)<<3) + (lane & 7));
    const uint32_t bbit = (uint32_t)((lane>>3) & 1);
    const uint32_t bsw  = (uint32_t)(lane & 7);
    const uint32_t vrow_l = (uint32_t)((lane & 7) + (((lane>>3)&1) << 3));
    const uint32_t vchk_l = (uint32_t)(lane >> 4);
    const int nkt = 2*qt + 2;

    attn_load(sb + 0*ASTG, b, h, 0);
    CP_COMMIT();
    attn_load(sb + 1*ASTG, b, h, 64);
    CP_COMMIT();
    if (nkt > 2) attn_load(sb + 2*ASTG, b, h, 128);
    CP_COMMIT();

    for (int kt=0; kt<nkt; kt++){
        CP_WAIT2();
        __syncthreads();
        if (kt+3 < nkt)
            attn_load(sb + ((kt+3)&3)*ASTG, b, h, (kt+3)*64);
        CP_COMMIT();    // always commit -> wait_group 2 stays exact

        const uint32_t st = sb + (kt&3)*ASTG;
        const int kbase = kt*64;

        // ---- S = (Qh+Ql) Kh^T (2 products) ----
        float S[8][4];
        #pragma unroll
        for (int j=0;j<8;j++){ S[j][0]=0.f; S[j][1]=0.f; S[j][2]=0.f; S[j][3]=0.f; }
        #pragma unroll
        for (int c=0;c<4;c++){
            const uint32_t coff = 16u*(((uint32_t)(2*c) | bbit) ^ bsw);
            uint32_t bKh[8][2];
            #pragma unroll
            for (int ntp=0; ntp<4; ntp++){
                uint32_t ad = st + (brow + (uint32_t)ntp*16)*128 + coff;
                ldsm4(ad, bKh[2*ntp][0], bKh[2*ntp][1], bKh[2*ntp+1][0], bKh[2*ntp+1][1]);
            }
            #pragma unroll
            for (int j=0;j<8;j++) mma16816(S[j], aQh[c], bKh[j]);
            #pragma unroll
            for (int j=0;j<8;j++) mma16816(S[j], aQl[c], bKh[j]);
        }

        // ---- scale + mask ----
        const bool need_mask = (kt >= 2*qt);
        #pragma unroll
        for (int j=0;j<8;j++){
            int col0 = kbase + j*8 + cq;
            #pragma unroll
            for (int e=0;e<4;e++){
                float v = S[j][e]*0.125f;
                if (need_mask){
                    int col = col0 + (e & 1);
                    int row = (e < 2) ? r1g : r2g;
                    if (col > row) v = -1e30f;
                }
                S[j][e] = v;
            }
        }

        // ---- online softmax ----
        float mx1=-1e30f, mx2=-1e30f;
        #pragma unroll
        for (int j=0;j<8;j++){
            mx1 = fmaxf(mx1, fmaxf(S[j][0], S[j][1]));
            mx2 = fmaxf(mx2, fmaxf(S[j][2], S[j][3]));
        }
        #pragma unroll
        for (int o=1;o<4;o<<=1){
            mx1 = fmaxf(mx1, __shfl_xor_sync(0xffffffffu, mx1, o));
            mx2 = fmaxf(mx2, __shfl_xor_sync(0xffffffffu, mx2, o));
        }
        float mn1 = fmaxf(m1, mx1), mn2 = fmaxf(m2, mx2);
        float co1 = __expf(m1 - mn1), co2 = __expf(m2 - mn2);
        float rs1 = 0.f, rs2 = 0.f;
        #pragma unroll
        for (int j=0;j<8;j++){
            S[j][0] = __expf(S[j][0]-mn1); S[j][1] = __expf(S[j][1]-mn1);
            S[j][2] = __expf(S[j][2]-mn2); S[j][3] = __expf(S[j][3]-mn2);
            rs1 += S[j][0] + S[j][1];
            rs2 += S[j][2] + S[j][3];
        }
        #pragma unroll
        for (int o=1;o<4;o<<=1){
            rs1 += __shfl_xor_sync(0xffffffffu, rs1, o);
            rs2 += __shfl_xor_sync(0xffffffffu, rs2, o);
        }
        l1 = l1*co1 + rs1;  m1 = mn1;
        l2 = l2*co2 + rs2;  m2 = mn2;
        #pragma unroll
        for (int j=0;j<8;j++){
            O[j][0]*=co1; O[j][1]*=co1; O[j][2]*=co2; O[j][3]*=co2;
        }

        // ---- pack P into A-fragments (hi/lo) ----
        uint32_t pH[4][4], pL[4][4];
        #pragma unroll
        for (int c=0;c<4;c++){
            packsplit(S[2*c][0],   S[2*c][1],   pH[c][0], pL[c][0]);
            packsplit(S[2*c][2],   S[2*c][3],   pH[c][1], pL[c][1]);
            packsplit(S[2*c+1][0], S[2*c+1][1], pH[c][2], pL[c][2]);
            packsplit(S[2*c+1][2], S[2*c+1][3], pH[c][3], pL[c][3]);
        }

        // ---- O += (pH+pL) Vh (2 products); V natural layout, trans ldmatrix ----
        #pragma unroll
        for (int c=0;c<4;c++){
            const uint32_t vrow = (uint32_t)(c*16) + vrow_l;
            uint32_t bVh[8][2];
            #pragma unroll
            for (int ntp=0; ntp<4; ntp++){
                uint32_t chunk = ((uint32_t)(2*ntp) + vchk_l) ^ (vrow & 7);
                uint32_t ad = st + APL + vrow*128 + 16u*chunk;
                ldsm4t(ad, bVh[2*ntp][0], bVh[2*ntp][1], bVh[2*ntp+1][0], bVh[2*ntp+1][1]);
            }
            #pragma unroll
            for (int j=0;j<8;j++) mma16816(O[j], pH[c], bVh[j]);
            #pragma unroll
            for (int j=0;j<8;j++) mma16816(O[j], pL[c], bVh[j]);
        }
    }

    const float i1 = 1.f/l1, i2 = 1.f/l2;
    const size_t ob1 = (size_t)(b*Tc + r1g)*Dc + h*HDc;
    const size_t ob2 = (size_t)(b*Tc + r2g)*Dc + h*HDc;
    #pragma unroll
    for (int j=0;j<8;j++){
        int col = j*8 + cq;
        split2(O[j][0]*i1, O[j][1]*i1, g_aH, g_aL, ob1 + col);
        split2(O[j][2]*i2, O[j][3]*i2, g_aH, g_aL, ob2 + col);
    }
}

// ---------------- final LayerNorm ----------------
__global__ void ln_kernel(const float* __restrict__ gamma, float* __restrict__ out){
    const int row = blockIdx.x, t = threadIdx.x;
    const float* x = g_x + (size_t)row*Dc;
    float4 xv = ((const float4*)x)[t];
    float s = xv.x+xv.y+xv.z+xv.w;
    __shared__ float red[16];
    #pragma unroll
    for (int o=16;o;o>>=1) s += __shfl_xor_sync(0xffffffffu, s, o);
    if ((t&31)==0) red[t>>5] = s;
    __syncthreads();
    float tot = 0.f;
    #pragma unroll
    for (int w=0;w<8;w++) tot += red[w];
    float mean = tot*(1.f/Dc);
    float dx=xv.x-mean, dy=xv.y-mean, dz=xv.z-mean, dw=xv.w-mean;
    float ss = dx*dx+dy*dy+dz*dz+dw*dw;
    #pragma unroll
    for (int o=16;o;o>>=1) ss += __shfl_xor_sync(0xffffffffu, ss, o);
    if ((t&31)==0) red[8+(t>>5)] = ss;
    __syncthreads();
    float tv = 0.f;
    #pragma unroll
    for (int w=0;w<8;w++) tv += red[8+w];
    float inv = rsqrtf(tv*(1.f/Dc) + 1e-5f);
    float4 g4 = ((const float4*)gamma)[t];
    float4 o4 = make_float4(dx*inv*g4.x, dy*inv*g4.y, dz*inv*g4.z, dw*inv*g4.w);
    ((float4*)out)[(size_t)row*(Dc/4) + t] = o4;
}

// ---------------- launch ----------------
extern "C" void kernel_launch(void* const* d_in, const int* in_sizes, int n_in,
                              void* d_out, int out_size)
{
    const float* q      = (const float*)d_in[0];
    const float* pos    = (const float*)d_in[1];
    const float* Wqkv   = (const float*)d_in[2];
    const float* convw  = (const float*)d_in[3];
    const float* projw  = (const float*)d_in[4];
    const float* fcw    = (const float*)d_in[5];
    const float* mlpw   = (const float*)d_in[6];
    const float* gamma  = (const float*)d_in[7];

    float *px;
    cudaGetSymbolAddress((void**)&px, g_x);
    __nv_bfloat16 *xH,*xL,*aH,*aL,*qkvH,*qkvL,*wqkvH,*wqkvL,*projH,*projL,*fcH,*fcL,*mlpH,*mlpL;
    cudaGetSymbolAddress((void**)&xH, g_xH);   cudaGetSymbolAddress((void**)&xL, g_xL);
    cudaGetSymbolAddress((void**)&aH, g_aH);   cudaGetSymbolAddress((void**)&aL, g_aL);
    cudaGetSymbolAddress((void**)&qkvH, g_qkvH); cudaGetSymbolAddress((void**)&qkvL, g_qkvL);
    cudaGetSymbolAddress((void**)&wqkvH, g_wqkvH); cudaGetSymbolAddress((void**)&wqkvL, g_wqkvL);
    cudaGetSymbolAddress((void**)&projH, g_projH); cudaGetSymbolAddress((void**)&projL, g_projL);
    cudaGetSymbolAddress((void**)&fcH, g_fcH);     cudaGetSymbolAddress((void**)&fcL, g_fcL);
    cudaGetSymbolAddress((void**)&mlpH, g_mlpH);   cudaGetSymbolAddress((void**)&mlpL, g_mlpL);

    cudaFuncSetAttribute(attn_mma, cudaFuncAttributeMaxDynamicSharedMemorySize, ATT_SMEM);
    cudaFuncSetAttribute(gemm_mma<EPI_QKV>,  cudaFuncAttributeMaxDynamicSharedMemorySize, GEMM_SMEM);
    cudaFuncSetAttribute(gemm_mma<EPI_ADD>,  cudaFuncAttributeMaxDynamicSharedMemorySize, GEMM_SMEM);
    cudaFuncSetAttribute(gemm_mma<EPI_GELU>, cudaFuncAttributeMaxDynamicSharedMemorySize, GEMM_SMEM);

    // split weights
    {
        int n4;
        n4 = Lc*3*Dc*Dc/4; split_kernel<<<n4/256, 256>>>(Wqkv, wqkvH, wqkvL, n4);
        n4 = Lc*Dc*Dc/4;   split_kernel<<<n4/256, 256>>>(projw, projH, projL, n4);
        n4 = Lc*FFc*Dc/4;  split_kernel<<<n4/256, 256>>>(fcw, fcH, fcL, n4);
        n4 = Lc*Dc*FFc/4;  split_kernel<<<n4/256, 256>>>(mlpw, mlpH, mlpL, n4);
    }

    posadd_kernel<<<Mc*Dc/4/256, 256>>>(q, pos);

    for (int l=0; l<Lc; l++){
        gemm_mma<EPI_QKV><<<dim3(3*Dc/128, Mc/128), 256, GEMM_SMEM>>>(
            xH, xL, wqkvH + (size_t)l*3*Dc*Dc, wqkvL + (size_t)l*3*Dc*Dc,
            convw + (size_t)l*3*Dc, nullptr, qkvH, qkvL, 3*Dc, Dc);
        attn_mma<<<dim3(Tc/128, Bc*Hc), 256, ATT_SMEM>>>();
        gemm_mma<EPI_ADD><<<dim3(Dc/128, Mc/128), 256, GEMM_SMEM>>>(
            aH, aL, projH + (size_t)l*Dc*Dc, projL + (size_t)l*Dc*Dc,
            px, px, xH, xL, Dc, Dc);
        gemm_mma<EPI_GELU><<<dim3(FFc/128, Mc/128), 256, GEMM_SMEM>>>(
            xH, xL, fcH + (size_t)l*FFc*Dc, fcL + (size_t)l*FFc*Dc,
            nullptr, nullptr, aH, aL, FFc, Dc);
        gemm_mma<EPI_ADD><<<dim3(Dc/128, Mc/128), 256, GEMM_SMEM>>>(
            aH, aL, mlpH + (size_t)l*Dc*FFc, mlpL + (size_t)l*Dc*FFc,
            px, px, xH, xL, Dc, FFc);
    }

    ln_kernel<<<Mc, 256>>>(gamma, (float*)d_out);
}

// round 14
// speedup vs baseline: 1.0692x; 1.0224x over previous
#include <cuda_runtime.h>
#include <cuda_bf16.h>
#include <math.h>
#include <stdint.h>

// Problem dims
#define Lc 8
#define Dc 1024
#define Hc 16
#define FFc 4096
#define Tc 2048
#define Bc 2
#define HDc 64
#define Mc (Bc*Tc)   // 4096 tokens

// ---------------- scratch (device globals) ----------------
__device__ float g_x[Mc*Dc];

__device__ __nv_bfloat16 g_xH[(size_t)Mc*Dc];
__device__ __nv_bfloat16 g_xL[(size_t)Mc*Dc];
__device__ __nv_bfloat16 g_aH[(size_t)Mc*FFc];
__device__ __nv_bfloat16 g_aL[(size_t)Mc*FFc];
__device__ __nv_bfloat16 g_qkvH[(size_t)Mc*3*Dc];   // q,k normalized; v scaled
__device__ __nv_bfloat16 g_qkvL[(size_t)Mc*3*Dc];
__device__ __nv_bfloat16 g_wqkvH[(size_t)Lc*3*Dc*Dc];
__device__ __nv_bfloat16 g_wqkvL[(size_t)Lc*3*Dc*Dc];
__device__ __nv_bfloat16 g_projH[(size_t)Lc*Dc*Dc];
__device__ __nv_bfloat16 g_projL[(size_t)Lc*Dc*Dc];
__device__ __nv_bfloat16 g_fcH[(size_t)Lc*FFc*Dc];
__device__ __nv_bfloat16 g_fcL[(size_t)Lc*FFc*Dc];
__device__ __nv_bfloat16 g_mlpH[(size_t)Lc*Dc*FFc];
__device__ __nv_bfloat16 g_mlpL[(size_t)Lc*Dc*FFc];

__device__ __forceinline__ float gelu_exact(float v){
    return 0.5f*v*(1.0f + erff(v*0.70710678118654752f));
}

// ---------------- PTX helpers ----------------
__device__ __forceinline__ uint32_t smem_u32(const void* p){
    uint32_t a;
    asm("{ .reg .u64 t; cvta.to.shared.u64 t, %1; cvt.u32.u64 %0, t; }" : "=r"(a) : "l"(p));
    return a;
}
#define CP_COMMIT()  asm volatile("cp.async.commit_group;" ::: "memory")
#define CP_WAIT1()   asm volatile("cp.async.wait_group 1;" ::: "memory")
#define CP_WAIT2()   asm volatile("cp.async.wait_group 2;" ::: "memory")
#define CP_WAIT0()   asm volatile("cp.async.wait_group 0;" ::: "memory")

__device__ __forceinline__ void cpasync16(uint32_t dst, const void* src){
    asm volatile("cp.async.cg.shared.global [%0], [%1], 16;" :: "r"(dst), "l"(src));
}
__device__ __forceinline__ void ldsm4(uint32_t addr, uint32_t& r0, uint32_t& r1, uint32_t& r2, uint32_t& r3){
    asm volatile("ldmatrix.sync.aligned.m8n8.x4.shared.b16 {%0,%1,%2,%3}, [%4];"
        : "=r"(r0), "=r"(r1), "=r"(r2), "=r"(r3) : "r"(addr));
}
__device__ __forceinline__ void ldsm4t(uint32_t addr, uint32_t& r0, uint32_t& r1, uint32_t& r2, uint32_t& r3){
    asm volatile("ldmatrix.sync.aligned.m8n8.x4.trans.shared.b16 {%0,%1,%2,%3}, [%4];"
        : "=r"(r0), "=r"(r1), "=r"(r2), "=r"(r3) : "r"(addr));
}
__device__ __forceinline__ void mma16816(float* c, const uint32_t* a, const uint32_t* b){
    asm volatile("mma.sync.aligned.m16n8k16.row.col.f32.bf16.bf16.f32 "
        "{%0,%1,%2,%3}, {%4,%5,%6,%7}, {%8,%9}, {%0,%1,%2,%3};"
        : "+f"(c[0]), "+f"(c[1]), "+f"(c[2]), "+f"(c[3])
        : "r"(a[0]), "r"(a[1]), "r"(a[2]), "r"(a[3]), "r"(b[0]), "r"(b[1]));
}

// ---------------- split helpers ----------------
__device__ __forceinline__ void split4(float4 v, __nv_bfloat16* hi, __nv_bfloat16* lo, size_t e){
    __nv_bfloat16 h0=__float2bfloat16(v.x), h1=__float2bfloat16(v.y);
    __nv_bfloat16 h2=__float2bfloat16(v.z), h3=__float2bfloat16(v.w);
    __nv_bfloat16 l0=__float2bfloat16(v.x-__bfloat162float(h0));
    __nv_bfloat16 l1=__float2bfloat16(v.y-__bfloat162float(h1));
    __nv_bfloat16 l2=__float2bfloat16(v.z-__bfloat162float(h2));
    __nv_bfloat16 l3=__float2bfloat16(v.w-__bfloat162float(h3));
    __nv_bfloat162 hp0; hp0.x=h0; hp0.y=h1;
    __nv_bfloat162 hp1; hp1.x=h2; hp1.y=h3;
    __nv_bfloat162 lp0; lp0.x=l0; lp0.y=l1;
    __nv_bfloat162 lp1; lp1.x=l2; lp1.y=l3;
    ((__nv_bfloat162*)hi)[e/2]   = hp0;
    ((__nv_bfloat162*)hi)[e/2+1] = hp1;
    ((__nv_bfloat162*)lo)[e/2]   = lp0;
    ((__nv_bfloat162*)lo)[e/2+1] = lp1;
}
__device__ __forceinline__ void split2(float x, float y, __nv_bfloat16* hi, __nv_bfloat16* lo, size_t e){
    __nv_bfloat16 h0=__float2bfloat16(x), h1=__float2bfloat16(y);
    __nv_bfloat16 l0=__float2bfloat16(x-__bfloat162float(h0));
    __nv_bfloat16 l1=__float2bfloat16(y-__bfloat162float(h1));
    __nv_bfloat162 hp; hp.x=h0; hp.y=h1;
    __nv_bfloat162 lp; lp.x=l0; lp.y=l1;
    ((__nv_bfloat162*)hi)[e/2] = hp;
    ((__nv_bfloat162*)lo)[e/2] = lp;
}
__device__ __forceinline__ void packsplit(float x, float y, uint32_t& h, uint32_t& l){
    __nv_bfloat16 hx=__float2bfloat16(x), hy=__float2bfloat16(y);
    __nv_bfloat16 lx=__float2bfloat16(x-__bfloat162float(hx));
    __nv_bfloat16 ly=__float2bfloat16(y-__bfloat162float(hy));
    __nv_bfloat162 hp; hp.x=hx; hp.y=hy;
    __nv_bfloat162 lp; lp.x=lx; lp.y=ly;
    h = *(uint32_t*)&hp; l = *(uint32_t*)&lp;
}

__global__ void split_kernel(const float* __restrict__ s, __nv_bfloat16* __restrict__ hi,
                             __nv_bfloat16* __restrict__ lo, int n4){
    int i = blockIdx.x*blockDim.x + threadIdx.x;
    if (i < n4){
        float4 v = ((const float4*)s)[i];
        split4(v, hi, lo, (size_t)i*4);
    }
}

// ---------------- pos add ----------------
__global__ void posadd_kernel(const float* __restrict__ q, const float* __restrict__ pos){
    int idx = blockIdx.x*blockDim.x + threadIdx.x;
    const int n4 = Mc*Dc/4;
    if (idx < n4){
        float4 a = ((const float4*)q)[idx];
        int pidx = idx % (Tc*Dc/4);
        float4 p = ((const float4*)pos)[pidx];
        a.x+=p.x; a.y+=p.y; a.z+=p.z; a.w+=p.w;
        ((float4*)g_x)[idx] = a;
        split4(a, g_xH, g_xL, (size_t)idx*4);
    }
}

// ---------------- HMMA GEMM (round-8 core; EPI_QKV fused scale+l2norm) --------
enum { EPI_QKV=0, EPI_ADD=1, EPI_GELU=2 };

#define PLANE 8192                 // 128 rows x 64B (swizzled)
#define STG   (4*PLANE)            // 32768
#define NSTAGE 3
#define GEMM_SMEM (NSTAGE*STG)     // 98304

__device__ __forceinline__ void load_stage(uint32_t sb,
    const __nv_bfloat16* __restrict__ pAh, const __nv_bfloat16* __restrict__ pAl,
    const __nv_bfloat16* __restrict__ pBh, const __nv_bfloat16* __restrict__ pBl,
    int K, int kb)
{
    const __nv_bfloat16* planes[4] = {pAh, pAl, pBh, pBl};
    const int tid = threadIdx.x;
    #pragma unroll
    for (int t=0; t<8; t++){
        int id = t*256 + tid;
        int plane = id >> 9;
        int rem = id & 511;
        int row = rem >> 2, c = rem & 3;
        uint32_t dst = sb + plane*PLANE + row*64 + 16*(c ^ ((row>>1)&3));
        cpasync16(dst, planes[plane] + (size_t)row*K + kb*32 + c*8);
    }
}

template<int EPI>
__global__ __launch_bounds__(256,2)
void gemm_mma(const __nv_bfloat16* __restrict__ Ah, const __nv_bfloat16* __restrict__ Al,
              const __nv_bfloat16* __restrict__ Bh, const __nv_bfloat16* __restrict__ Bl,
              const float* __restrict__ aux, float* __restrict__ C,
              __nv_bfloat16* __restrict__ Oh, __nv_bfloat16* __restrict__ Ol,
              int N, int K)
{
    extern __shared__ char smem[];
    const uint32_t sbase = smem_u32(smem);
    const int tid = threadIdx.x;
    const int wid = tid >> 5, lane = tid & 31;
    const int wm = wid >> 1, wn = wid & 1;
    const int bm = blockIdx.y*128, bn = blockIdx.x*128;
    const int KB = K >> 5;

    const __nv_bfloat16* pAh = Ah + (size_t)bm*K;
    const __nv_bfloat16* pAl = Al + (size_t)bm*K;
    const __nv_bfloat16* pBh = Bh + (size_t)bn*K;
    const __nv_bfloat16* pBl = Bl + (size_t)bn*K;

    float acc[2][8][4];
    #pragma unroll
    for (int i=0;i<2;i++)
        #pragma unroll
        for (int j=0;j<8;j++)
            #pragma unroll
            for (int k=0;k<4;k++) acc[i][j][k]=0.f;

    const uint32_t s_lane = (lane >> 1) & 3;
    const uint32_t rowA = (uint32_t)(wm*32 + (lane & 15));
    const uint32_t aoff0 = rowA*64 + 16u*(((0u) | (uint32_t)(lane>>4)) ^ s_lane);
    const uint32_t aoff1 = rowA*64 + 16u*(((2u) | (uint32_t)(lane>>4)) ^ s_lane);
    const uint32_t rowB = (uint32_t)(wn*64 + ((lane>>4)<<3) + (lane & 7));
    const uint32_t bbit = (uint32_t)((lane>>3) & 1);
    const uint32_t boff0 = rowB*64 + 16u*(((0u) | bbit) ^ s_lane);
    const uint32_t boff1 = rowB*64 + 16u*(((2u) | bbit) ^ s_lane);

    load_stage(sbase + 0*STG, pAh, pAl, pBh, pBl, K, 0);
    CP_COMMIT();
    load_stage(sbase + 1*STG, pAh, pAl, pBh, pBl, K, 1);
    CP_COMMIT();

    int cur = 0, nxt2 = 2;
    for (int kb=0; kb<KB; kb++){
        if (kb+1 < KB) CP_WAIT1(); else CP_WAIT0();
        __syncthreads();
        if (kb+2 < KB){
            load_stage(sbase + nxt2*STG, pAh, pAl, pBh, pBl, K, kb+2);
            CP_COMMIT();
        }

        const uint32_t sb = sbase + cur*STG;
        #pragma unroll
        for (int ks=0; ks<2; ks++){
            const uint32_t aoff = ks ? aoff1 : aoff0;
            const uint32_t boff = ks ? boff1 : boff0;
            uint32_t aH[2][4], aL[2][4];
            #pragma unroll
            for (int mt=0; mt<2; mt++){
                uint32_t ad = sb + aoff + (uint32_t)mt*1024;
                ldsm4(ad, aH[mt][0], aH[mt][1], aH[mt][2], aH[mt][3]);
                ldsm4(ad + PLANE, aL[mt][0], aL[mt][1], aL[mt][2], aL[mt][3]);
            }
            #pragma unroll
            for (int nh=0; nh<2; nh++){
                uint32_t bH[4][2], bL[4][2];
                #pragma unroll
                for (int np=0; np<2; np++){
                    int ntp = nh*2 + np;
                    uint32_t bd = sb + 2*PLANE + boff + (uint32_t)ntp*1024;
                    ldsm4(bd, bH[2*np][0], bH[2*np][1], bH[2*np+1][0], bH[2*np+1][1]);
                    ldsm4(bd + PLANE, bL[2*np][0], bL[2*np][1], bL[2*np+1][0], bL[2*np+1][1]);
                }
                #pragma unroll
                for (int mt=0; mt<2; mt++)
                    #pragma unroll
                    for (int nt=0; nt<4; nt++)
                        mma16816(acc[mt][nh*4+nt], aH[mt], bH[nt]);
                #pragma unroll
                for (int mt=0; mt<2; mt++)
                    #pragma unroll
                    for (int nt=0; nt<4; nt++)
                        mma16816(acc[mt][nh*4+nt], aH[mt], bL[nt]);
                #pragma unroll
                for (int mt=0; mt<2; mt++)
                    #pragma unroll
                    for (int nt=0; nt<4; nt++)
                        mma16816(acc[mt][nh*4+nt], aL[mt], bH[nt]);
            }
        }
        cur = (cur == 2) ? 0 : cur+1;
        nxt2 = (nxt2 == 2) ? 0 : nxt2+1;
    }

    const int rbase = bm + wm*32 + (lane>>2);
    const int cbase = bn + wn*64 + (lane&3)*2;

    if (EPI == EPI_QKV){
        const bool isqk = (bn < 2*Dc);
        #pragma unroll
        for (int mt=0; mt<2; mt++){
            #pragma unroll
            for (int half=0; half<2; half++){
                const int row = rbase + mt*16 + half*8;
                float vx[8], vy[8];
                float ss = 0.f;
                #pragma unroll
                for (int nt=0; nt<8; nt++){
                    const int col = cbase + nt*8;
                    float2 sc = *(const float2*)&aux[col];
                    float x = acc[mt][nt][half*2+0]*sc.x;
                    float y = acc[mt][nt][half*2+1]*sc.y;
                    vx[nt] = x; vy[nt] = y;
                    ss += x*x + y*y;
                }
                if (isqk){
                    ss += __shfl_xor_sync(0xffffffffu, ss, 1);
                    ss += __shfl_xor_sync(0xffffffffu, ss, 2);
                    float inv = 1.f / fmaxf(sqrtf(ss), 1e-5f);
                    #pragma unroll
                    for (int nt=0; nt<8; nt++){ vx[nt]*=inv; vy[nt]*=inv; }
                }
                #pragma unroll
                for (int nt=0; nt<8; nt++){
                    const int col = cbase + nt*8;
                    split2(vx[nt], vy[nt], Oh, Ol, (size_t)row*N + col);
                }
            }
        }
    } else {
        #pragma unroll
        for (int mt=0; mt<2; mt++){
            #pragma unroll
            for (int nt=0; nt<8; nt++){
                const int col = cbase + nt*8;
                #pragma unroll
                for (int half=0; half<2; half++){
                    const int row = rbase + mt*16 + half*8;
                    float vxx = acc[mt][nt][half*2+0];
                    float vyy = acc[mt][nt][half*2+1];
                    if (EPI == EPI_ADD){
                        float2 r = *(const float2*)&aux[(size_t)row*N + col];
                        vxx += r.x; vyy += r.y;
                        *(float2*)&C[(size_t)row*N + col] = make_float2(vxx, vyy);
                        split2(vxx, vyy, Oh, Ol, (size_t)row*N + col);
                    } else {
                        vxx = gelu_exact(vxx); vyy = gelu_exact(vyy);
                        split2(vxx, vyy, Oh, Ol, (size_t)row*N + col);
                    }
                }
            }
        }
    }
}

// ---------------- HMMA flash attention: BM=128, BN=64, SW128 swizzle,
//  S = Qh.Kh (1 product, logit-path drops proven free); PV = (pH+pL).Vh --------
#define APL 8192                   // 64 rows x 128B swizzled
#define ASTG (2*APL)               // 16384  (Kh, Vh)
#define NATT 4
#define ATT_SMEM (NATT*ASTG)       // 65536

__device__ __forceinline__ void attn_load(uint32_t s0, int b, int h, int kbase){
    const int tid = threadIdx.x;
    #pragma unroll
    for (int t=0; t<4; t++){
        int id = t*256 + tid;          // 0..1023
        int plane = id >> 9;           // 0=Kh, 1=Vh
        int rem = id & 511;
        int row = rem >> 3, c = rem & 7;
        uint32_t dst = s0 + plane*APL + row*128 + 16*(c ^ (row & 7));
        const __nv_bfloat16* src = g_qkvH + (size_t)(b*Tc + kbase + row)*(3*Dc)
                                 + ((plane == 0) ? Dc : 2*Dc) + h*HDc + c*8;
        cpasync16(dst, src);
    }
}

__global__ __launch_bounds__(256)
void attn_mma(){
    extern __shared__ char smc[];
    const uint32_t sb = smem_u32(smc);
    const int tid = threadIdx.x;
    const int wid = tid >> 5, lane = tid & 31;
    const int qt = (int)gridDim.x - 1 - (int)blockIdx.x;     // heavy CTAs first
    const int bh = blockIdx.y, b = bh >> 4, h = bh & 15;
    const int qbase = qt*128;
    const int wrow = qbase + wid*16;
    const int cq = (lane & 3)*2;
    const int r1g = wrow + (lane >> 2), r2g = r1g + 8;

    uint32_t aQh[4][4];
    {
        const size_t rb1 = (size_t)(b*Tc + r1g)*(3*Dc) + h*HDc;
        const size_t rb2 = (size_t)(b*Tc + r2g)*(3*Dc) + h*HDc;
        #pragma unroll
        for (int c=0;c<4;c++){
            int col = 16*c + cq;
            aQh[c][0] = *(const uint32_t*)&g_qkvH[rb1 + col];
            aQh[c][1] = *(const uint32_t*)&g_qkvH[rb2 + col];
            aQh[c][2] = *(const uint32_t*)&g_qkvH[rb1 + col + 8];
            aQh[c][3] = *(const uint32_t*)&g_qkvH[rb2 + col + 8];
        }
    }

    float O[8][4];
    #pragma unroll
    for (int j=0;j<8;j++){ O[j][0]=0.f; O[j][1]=0.f; O[j][2]=0.f; O[j][3]=0.f; }
    float m1=-1e30f, m2=-1e30f, l1=0.f, l2=0.f;

    const uint32_t brow = (uint32_t)(((lane>>4)<<3) + (lane & 7));
    const uint32_t bbit = (uint32_t)((lane>>3) & 1);
    const uint32_t bsw  = (uint32_t)(lane & 7);
    const uint32_t vrow_l = (uint32_t)((lane & 7) + (((lane>>3)&1) << 3));
    const uint32_t vchk_l = (uint32_t)(lane >> 4);
    const int nkt = 2*qt + 2;

    attn_load(sb + 0*ASTG, b, h, 0);
    CP_COMMIT();
    attn_load(sb + 1*ASTG, b, h, 64);
    CP_COMMIT();
    if (nkt > 2) attn_load(sb + 2*ASTG, b, h, 128);
    CP_COMMIT();

    for (int kt=0; kt<nkt; kt++){
        CP_WAIT2();
        __syncthreads();
        if (kt+3 < nkt)
            attn_load(sb + ((kt+3)&3)*ASTG, b, h, (kt+3)*64);
        CP_COMMIT();    // always commit -> wait_group 2 stays exact

        const uint32_t st = sb + (kt&3)*ASTG;
        const int kbase = kt*64;

        // ---- S = Qh Kh^T (1 product) ----
        float S[8][4];
        #pragma unroll
        for (int j=0;j<8;j++){ S[j][0]=0.f; S[j][1]=0.f; S[j][2]=0.f; S[j][3]=0.f; }
        #pragma unroll
        for (int c=0;c<4;c++){
            const uint32_t coff = 16u*(((uint32_t)(2*c) | bbit) ^ bsw);
            uint32_t bKh[8][2];
            #pragma unroll
            for (int ntp=0; ntp<4; ntp++){
                uint32_t ad = st + (brow + (uint32_t)ntp*16)*128 + coff;
                ldsm4(ad, bKh[2*ntp][0], bKh[2*ntp][1], bKh[2*ntp+1][0], bKh[2*ntp+1][1]);
            }
            #pragma unroll
            for (int j=0;j<8;j++) mma16816(S[j], aQh[c], bKh[j]);
        }

        // ---- scale + mask ----
        const bool need_mask = (kt >= 2*qt);
        #pragma unroll
        for (int j=0;j<8;j++){
            int col0 = kbase + j*8 + cq;
            #pragma unroll
            for (int e=0;e<4;e++){
                float v = S[j][e]*0.125f;
                if (need_mask){
                    int col = col0 + (e & 1);
                    int row = (e < 2) ? r1g : r2g;
                    if (col > row) v = -1e30f;
                }
                S[j][e] = v;
            }
        }

        // ---- online softmax ----
        float mx1=-1e30f, mx2=-1e30f;
        #pragma unroll
        for (int j=0;j<8;j++){
            mx1 = fmaxf(mx1, fmaxf(S[j][0], S[j][1]));
            mx2 = fmaxf(mx2, fmaxf(S[j][2], S[j][3]));
        }
        #pragma unroll
        for (int o=1;o<4;o<<=1){
            mx1 = fmaxf(mx1, __shfl_xor_sync(0xffffffffu, mx1, o));
            mx2 = fmaxf(mx2, __shfl_xor_sync(0xffffffffu, mx2, o));
        }
        float mn1 = fmaxf(m1, mx1), mn2 = fmaxf(m2, mx2);
        float co1 = __expf(m1 - mn1), co2 = __expf(m2 - mn2);
        float rs1 = 0.f, rs2 = 0.f;
        #pragma unroll
        for (int j=0;j<8;j++){
            S[j][0] = __expf(S[j][0]-mn1); S[j][1] = __expf(S[j][1]-mn1);
            S[j][2] = __expf(S[j][2]-mn2); S[j][3] = __expf(S[j][3]-mn2);
            rs1 += S[j][0] + S[j][1];
            rs2 += S[j][2] + S[j][3];
        }
        #pragma unroll
        for (int o=1;o<4;o<<=1){
            rs1 += __shfl_xor_sync(0xffffffffu, rs1, o);
            rs2 += __shfl_xor_sync(0xffffffffu, rs2, o);
        }
        l1 = l1*co1 + rs1;  m1 = mn1;
        l2 = l2*co2 + rs2;  m2 = mn2;
        #pragma unroll
        for (int j=0;j<8;j++){
            O[j][0]*=co1; O[j][1]*=co1; O[j][2]*=co2; O[j][3]*=co2;
        }

        // ---- pack P into A-fragments (hi/lo) ----
        uint32_t pH[4][4], pL[4][4];
        #pragma unroll
        for (int c=0;c<4;c++){
            packsplit(S[2*c][0],   S[2*c][1],   pH[c][0], pL[c][0]);
            packsplit(S[2*c][2],   S[2*c][3],   pH[c][1], pL[c][1]);
            packsplit(S[2*c+1][0], S[2*c+1][1], pH[c][2], pL[c][2]);
            packsplit(S[2*c+1][2], S[2*c+1][3], pH[c][3], pL[c][3]);
        }

        // ---- O += (pH+pL) Vh (2 products); V natural layout, trans ldmatrix ----
        #pragma unroll
        for (int c=0;c<4;c++){
            const uint32_t vrow = (uint32_t)(c*16) + vrow_l;
            uint32_t bVh[8][2];
            #pragma unroll
            for (int ntp=0; ntp<4; ntp++){
                uint32_t chunk = ((uint32_t)(2*ntp) + vchk_l) ^ (vrow & 7);
                uint32_t ad = st + APL + vrow*128 + 16u*chunk;
                ldsm4t(ad, bVh[2*ntp][0], bVh[2*ntp][1], bVh[2*ntp+1][0], bVh[2*ntp+1][1]);
            }
            #pragma unroll
            for (int j=0;j<8;j++) mma16816(O[j], pH[c], bVh[j]);
            #pragma unroll
            for (int j=0;j<8;j++) mma16816(O[j], pL[c], bVh[j]);
        }
    }

    const float i1 = 1.f/l1, i2 = 1.f/l2;
    const size_t ob1 = (size_t)(b*Tc + r1g)*Dc + h*HDc;
    const size_t ob2 = (size_t)(b*Tc + r2g)*Dc + h*HDc;
    #pragma unroll
    for (int j=0;j<8;j++){
        int col = j*8 + cq;
        split2(O[j][0]*i1, O[j][1]*i1, g_aH, g_aL, ob1 + col);
        split2(O[j][2]*i2, O[j][3]*i2, g_aH, g_aL, ob2 + col);
    }
}

// ---------------- final LayerNorm ----------------
__global__ void ln_kernel(const float* __restrict__ gamma, float* __restrict__ out){
    const int row = blockIdx.x, t = threadIdx.x;
    const float* x = g_x + (size_t)row*Dc;
    float4 xv = ((const float4*)x)[t];
    float s = xv.x+xv.y+xv.z+xv.w;
    __shared__ float red[16];
    #pragma unroll
    for (int o=16;o;o>>=1) s += __shfl_xor_sync(0xffffffffu, s, o);
    if ((t&31)==0) red[t>>5] = s;
    __syncthreads();
    float tot = 0.f;
    #pragma unroll
    for (int w=0;w<8;w++) tot += red[w];
    float mean = tot*(1.f/Dc);
    float dx=xv.x-mean, dy=xv.y-mean, dz=xv.z-mean, dw=xv.w-mean;
    float ss = dx*dx+dy*dy+dz*dz+dw*dw;
    #pragma unroll
    for (int o=16;o;o>>=1) ss += __shfl_xor_sync(0xffffffffu, ss, o);
    if ((t&31)==0) red[8+(t>>5)] = ss;
    __syncthreads();
    float tv = 0.f;
    #pragma unroll
    for (int w=0;w<8;w++) tv += red[8+w];
    float inv = rsqrtf(tv*(1.f/Dc) + 1e-5f);
    float4 g4 = ((const float4*)gamma)[t];
    float4 o4 = make_float4(dx*inv*g4.x, dy*inv*g4.y, dz*inv*g4.z, dw*inv*g4.w);
    ((float4*)out)[(size_t)row*(Dc/4) + t] = o4;
}

// ---------------- launch ----------------
extern "C" void kernel_launch(void* const* d_in, const int* in_sizes, int n_in,
                              void* d_out, int out_size)
{
    const float* q      = (const float*)d_in[0];
    const float* pos    = (const float*)d_in[1];
    const float* Wqkv   = (const float*)d_in[2];
    const float* convw  = (const float*)d_in[3];
    const float* projw  = (const float*)d_in[4];
    const float* fcw    = (const float*)d_in[5];
    const float* mlpw   = (const float*)d_in[6];
    const float* gamma  = (const float*)d_in[7];

    float *px;
    cudaGetSymbolAddress((void**)&px, g_x);
    __nv_bfloat16 *xH,*xL,*aH,*aL,*qkvH,*qkvL,*wqkvH,*wqkvL,*projH,*projL,*fcH,*fcL,*mlpH,*mlpL;
    cudaGetSymbolAddress((void**)&xH, g_xH);   cudaGetSymbolAddress((void**)&xL, g_xL);
    cudaGetSymbolAddress((void**)&aH, g_aH);   cudaGetSymbolAddress((void**)&aL, g_aL);
    cudaGetSymbolAddress((void**)&qkvH, g_qkvH); cudaGetSymbolAddress((void**)&qkvL, g_qkvL);
    cudaGetSymbolAddress((void**)&wqkvH, g_wqkvH); cudaGetSymbolAddress((void**)&wqkvL, g_wqkvL);
    cudaGetSymbolAddress((void**)&projH, g_projH); cudaGetSymbolAddress((void**)&projL, g_projL);
    cudaGetSymbolAddress((void**)&fcH, g_fcH);     cudaGetSymbolAddress((void**)&fcL, g_fcL);
    cudaGetSymbolAddress((void**)&mlpH, g_mlpH);   cudaGetSymbolAddress((void**)&mlpL, g_mlpL);

    cudaFuncSetAttribute(attn_mma, cudaFuncAttributeMaxDynamicSharedMemorySize, ATT_SMEM);
    cudaFuncSetAttribute(gemm_mma<EPI_QKV>,  cudaFuncAttributeMaxDynamicSharedMemorySize, GEMM_SMEM);
    cudaFuncSetAttribute(gemm_mma<EPI_ADD>,  cudaFuncAttributeMaxDynamicSharedMemorySize, GEMM_SMEM);
    cudaFuncSetAttribute(gemm_mma<EPI_GELU>, cudaFuncAttributeMaxDynamicSharedMemorySize, GEMM_SMEM);

    // split weights
    {
        int n4;
        n4 = Lc*3*Dc*Dc/4; split_kernel<<<n4/256, 256>>>(Wqkv, wqkvH, wqkvL, n4);
        n4 = Lc*Dc*Dc/4;   split_kernel<<<n4/256, 256>>>(projw, projH, projL, n4);
        n4 = Lc*FFc*Dc/4;  split_kernel<<<n4/256, 256>>>(fcw, fcH, fcL, n4);
        n4 = Lc*Dc*FFc/4;  split_kernel<<<n4/256, 256>>>(mlpw, mlpH, mlpL, n4);
    }

    posadd_kernel<<<Mc*Dc/4/256, 256>>>(q, pos);

    for (int l=0; l<Lc; l++){
        gemm_mma<EPI_QKV><<<dim3(3*Dc/128, Mc/128), 256, GEMM_SMEM>>>(
            xH, xL, wqkvH + (size_t)l*3*Dc*Dc, wqkvL + (size_t)l*3*Dc*Dc,
            convw + (size_t)l*3*Dc, nullptr, qkvH, qkvL, 3*Dc, Dc);
        attn_mma<<<dim3(Tc/128, Bc*Hc), 256, ATT_SMEM>>>();
        gemm_mma<EPI_ADD><<<dim3(Dc/128, Mc/128), 256, GEMM_SMEM>>>(
            aH, aL, projH + (size_t)l*Dc*Dc, projL + (size_t)l*Dc*Dc,
            px, px, xH, xL, Dc, Dc);
        gemm_mma<EPI_GELU><<<dim3(FFc/128, Mc/128), 256, GEMM_SMEM>>>(
            xH, xL, fcH + (size_t)l*FFc*Dc, fcL + (size_t)l*FFc*Dc,
            nullptr, nullptr, aH, aL, FFc, Dc);
        gemm_mma<EPI_ADD><<<dim3(Dc/128, Mc/128), 256, GEMM_SMEM>>>(
            aH, aL, mlpH + (size_t)l*Dc*FFc, mlpL + (size_t)l*Dc*FFc,
            px, px, xH, xL, Dc, FFc);
    }

    ln_kernel<<<Mc, 256>>>(gamma, (float*)d_out);
}

// round 15
// speedup vs baseline: 1.1084x; 1.0366x over previous
#include <cuda_runtime.h>
#include <cuda_bf16.h>
#include <math.h>
#include <stdint.h>

// Problem dims
#define Lc 8
#define Dc 1024
#define Hc 16
#define FFc 4096
#define Tc 2048
#define Bc 2
#define HDc 64
#define Mc (Bc*Tc)   // 4096 tokens

// ---------------- scratch (device globals) ----------------
__device__ float g_x[Mc*Dc];

__device__ __nv_bfloat16 g_xH[(size_t)Mc*Dc];
__device__ __nv_bfloat16 g_xL[(size_t)Mc*Dc];
__device__ __nv_bfloat16 g_aH[(size_t)Mc*FFc];
__device__ __nv_bfloat16 g_aL[(size_t)Mc*FFc];
__device__ __nv_bfloat16 g_qkvH[(size_t)Mc*3*Dc];   // q,k normalized; v scaled
__device__ __nv_bfloat16 g_qkvL[(size_t)Mc*3*Dc];
__device__ __nv_bfloat16 g_wqkvH[(size_t)Lc*3*Dc*Dc];
__device__ __nv_bfloat16 g_wqkvL[(size_t)Lc*3*Dc*Dc];
__device__ __nv_bfloat16 g_projH[(size_t)Lc*Dc*Dc];
__device__ __nv_bfloat16 g_projL[(size_t)Lc*Dc*Dc];
__device__ __nv_bfloat16 g_fcH[(size_t)Lc*FFc*Dc];
__device__ __nv_bfloat16 g_fcL[(size_t)Lc*FFc*Dc];
__device__ __nv_bfloat16 g_mlpH[(size_t)Lc*Dc*FFc];
__device__ __nv_bfloat16 g_mlpL[(size_t)Lc*Dc*FFc];

__device__ __forceinline__ float gelu_exact(float v){
    return 0.5f*v*(1.0f + erff(v*0.70710678118654752f));
}

// ---------------- PTX helpers ----------------
__device__ __forceinline__ uint32_t smem_u32(const void* p){
    uint32_t a;
    asm("{ .reg .u64 t; cvta.to.shared.u64 t, %1; cvt.u32.u64 %0, t; }" : "=r"(a) : "l"(p));
    return a;
}
#define CP_COMMIT()  asm volatile("cp.async.commit_group;" ::: "memory")
#define CP_WAIT1()   asm volatile("cp.async.wait_group 1;" ::: "memory")
#define CP_WAIT2()   asm volatile("cp.async.wait_group 2;" ::: "memory")
#define CP_WAIT0()   asm volatile("cp.async.wait_group 0;" ::: "memory")

__device__ __forceinline__ void cpasync16(uint32_t dst, const void* src){
    asm volatile("cp.async.cg.shared.global [%0], [%1], 16;" :: "r"(dst), "l"(src));
}
__device__ __forceinline__ void ldsm4(uint32_t addr, uint32_t& r0, uint32_t& r1, uint32_t& r2, uint32_t& r3){
    asm volatile("ldmatrix.sync.aligned.m8n8.x4.shared.b16 {%0,%1,%2,%3}, [%4];"
        : "=r"(r0), "=r"(r1), "=r"(r2), "=r"(r3) : "r"(addr));
}
__device__ __forceinline__ void ldsm4t(uint32_t addr, uint32_t& r0, uint32_t& r1, uint32_t& r2, uint32_t& r3){
    asm volatile("ldmatrix.sync.aligned.m8n8.x4.trans.shared.b16 {%0,%1,%2,%3}, [%4];"
        : "=r"(r0), "=r"(r1), "=r"(r2), "=r"(r3) : "r"(addr));
}
__device__ __forceinline__ void mma16816(float* c, const uint32_t* a, const uint32_t* b){
    asm volatile("mma.sync.aligned.m16n8k16.row.col.f32.bf16.bf16.f32 "
        "{%0,%1,%2,%3}, {%4,%5,%6,%7}, {%8,%9}, {%0,%1,%2,%3};"
        : "+f"(c[0]), "+f"(c[1]), "+f"(c[2]), "+f"(c[3])
        : "r"(a[0]), "r"(a[1]), "r"(a[2]), "r"(a[3]), "r"(b[0]), "r"(b[1]));
}

// ---------------- split helpers ----------------
__device__ __forceinline__ void split4(float4 v, __nv_bfloat16* hi, __nv_bfloat16* lo, size_t e){
    __nv_bfloat16 h0=__float2bfloat16(v.x), h1=__float2bfloat16(v.y);
    __nv_bfloat16 h2=__float2bfloat16(v.z), h3=__float2bfloat16(v.w);
    __nv_bfloat16 l0=__float2bfloat16(v.x-__bfloat162float(h0));
    __nv_bfloat16 l1=__float2bfloat16(v.y-__bfloat162float(h1));
    __nv_bfloat16 l2=__float2bfloat16(v.z-__bfloat162float(h2));
    __nv_bfloat16 l3=__float2bfloat16(v.w-__bfloat162float(h3));
    __nv_bfloat162 hp0; hp0.x=h0; hp0.y=h1;
    __nv_bfloat162 hp1; hp1.x=h2; hp1.y=h3;
    __nv_bfloat162 lp0; lp0.x=l0; lp0.y=l1;
    __nv_bfloat162 lp1; lp1.x=l2; lp1.y=l3;
    ((__nv_bfloat162*)hi)[e/2]   = hp0;
    ((__nv_bfloat162*)hi)[e/2+1] = hp1;
    ((__nv_bfloat162*)lo)[e/2]   = lp0;
    ((__nv_bfloat162*)lo)[e/2+1] = lp1;
}
__device__ __forceinline__ void split2(float x, float y, __nv_bfloat16* hi, __nv_bfloat16* lo, size_t e){
    __nv_bfloat16 h0=__float2bfloat16(x), h1=__float2bfloat16(y);
    __nv_bfloat16 l0=__float2bfloat16(x-__bfloat162float(h0));
    __nv_bfloat16 l1=__float2bfloat16(y-__bfloat162float(h1));
    __nv_bfloat162 hp; hp.x=h0; hp.y=h1;
    __nv_bfloat162 lp; lp.x=l0; lp.y=l1;
    ((__nv_bfloat162*)hi)[e/2] = hp;
    ((__nv_bfloat162*)lo)[e/2] = lp;
}
__device__ __forceinline__ uint32_t pack2(float x, float y){
    __nv_bfloat162 hp; hp.x=__float2bfloat16(x); hp.y=__float2bfloat16(y);
    return *(uint32_t*)&hp;
}

__global__ void split_kernel(const float* __restrict__ s, __nv_bfloat16* __restrict__ hi,
                             __nv_bfloat16* __restrict__ lo, int n4){
    int i = blockIdx.x*blockDim.x + threadIdx.x;
    if (i < n4){
        float4 v = ((const float4*)s)[i];
        split4(v, hi, lo, (size_t)i*4);
    }
}

// ---------------- pos add ----------------
__global__ void posadd_kernel(const float* __restrict__ q, const float* __restrict__ pos){
    int idx = blockIdx.x*blockDim.x + threadIdx.x;
    const int n4 = Mc*Dc/4;
    if (idx < n4){
        float4 a = ((const float4*)q)[idx];
        int pidx = idx % (Tc*Dc/4);
        float4 p = ((const float4*)pos)[pidx];
        a.x+=p.x; a.y+=p.y; a.z+=p.z; a.w+=p.w;
        ((float4*)g_x)[idx] = a;
        split4(a, g_xH, g_xL, (size_t)idx*4);
    }
}

// ---------------- HMMA GEMM (round-8 core; EPI_QKV fused scale+l2norm) --------
enum { EPI_QKV=0, EPI_ADD=1, EPI_GELU=2 };

#define PLANE 8192                 // 128 rows x 64B (swizzled)
#define STG   (4*PLANE)            // 32768
#define NSTAGE 3
#define GEMM_SMEM (NSTAGE*STG)     // 98304

__device__ __forceinline__ void load_stage(uint32_t sb,
    const __nv_bfloat16* __restrict__ pAh, const __nv_bfloat16* __restrict__ pAl,
    const __nv_bfloat16* __restrict__ pBh, const __nv_bfloat16* __restrict__ pBl,
    int K, int kb)
{
    const __nv_bfloat16* planes[4] = {pAh, pAl, pBh, pBl};
    const int tid = threadIdx.x;
    #pragma unroll
    for (int t=0; t<8; t++){
        int id = t*256 + tid;
        int plane = id >> 9;
        int rem = id & 511;
        int row = rem >> 2, c = rem & 3;
        uint32_t dst = sb + plane*PLANE + row*64 + 16*(c ^ ((row>>1)&3));
        cpasync16(dst, planes[plane] + (size_t)row*K + kb*32 + c*8);
    }
}

template<int EPI>
__global__ __launch_bounds__(256,2)
void gemm_mma(const __nv_bfloat16* __restrict__ Ah, const __nv_bfloat16* __restrict__ Al,
              const __nv_bfloat16* __restrict__ Bh, const __nv_bfloat16* __restrict__ Bl,
              const float* __restrict__ aux, float* __restrict__ C,
              __nv_bfloat16* __restrict__ Oh, __nv_bfloat16* __restrict__ Ol,
              int N, int K)
{
    extern __shared__ char smem[];
    const uint32_t sbase = smem_u32(smem);
    const int tid = threadIdx.x;
    const int wid = tid >> 5, lane = tid & 31;
    const int wm = wid >> 1, wn = wid & 1;
    const int bm = blockIdx.y*128, bn = blockIdx.x*128;
    const int KB = K >> 5;

    const __nv_bfloat16* pAh = Ah + (size_t)bm*K;
    const __nv_bfloat16* pAl = Al + (size_t)bm*K;
    const __nv_bfloat16* pBh = Bh + (size_t)bn*K;
    const __nv_bfloat16* pBl = Bl + (size_t)bn*K;

    float acc[2][8][4];
    #pragma unroll
    for (int i=0;i<2;i++)
        #pragma unroll
        for (int j=0;j<8;j++)
            #pragma unroll
            for (int k=0;k<4;k++) acc[i][j][k]=0.f;

    const uint32_t s_lane = (lane >> 1) & 3;
    const uint32_t rowA = (uint32_t)(wm*32 + (lane & 15));
    const uint32_t aoff0 = rowA*64 + 16u*(((0u) | (uint32_t)(lane>>4)) ^ s_lane);
    const uint32_t aoff1 = rowA*64 + 16u*(((2u) | (uint32_t)(lane>>4)) ^ s_lane);
    const uint32_t rowB = (uint32_t)(wn*64 + ((lane>>4)<<3) + (lane & 7));
    const uint32_t bbit = (uint32_t)((lane>>3) & 1);
    const uint32_t boff0 = rowB*64 + 16u*(((0u) | bbit) ^ s_lane);
    const uint32_t boff1 = rowB*64 + 16u*(((2u) | bbit) ^ s_lane);

    load_stage(sbase + 0*STG, pAh, pAl, pBh, pBl, K, 0);
    CP_COMMIT();
    load_stage(sbase + 1*STG, pAh, pAl, pBh, pBl, K, 1);
    CP_COMMIT();

    int cur = 0, nxt2 = 2;
    for (int kb=0; kb<KB; kb++){
        if (kb+1 < KB) CP_WAIT1(); else CP_WAIT0();
        __syncthreads();
        if (kb+2 < KB){
            load_stage(sbase + nxt2*STG, pAh, pAl, pBh, pBl, K, kb+2);
            CP_COMMIT();
        }

        const uint32_t sb = sbase + cur*STG;
        #pragma unroll
        for (int ks=0; ks<2; ks++){
            const uint32_t aoff = ks ? aoff1 : aoff0;
            const uint32_t boff = ks ? boff1 : boff0;
            uint32_t aH[2][4], aL[2][4];
            #pragma unroll
            for (int mt=0; mt<2; mt++){
                uint32_t ad = sb + aoff + (uint32_t)mt*1024;
                ldsm4(ad, aH[mt][0], aH[mt][1], aH[mt][2], aH[mt][3]);
                ldsm4(ad + PLANE, aL[mt][0], aL[mt][1], aL[mt][2], aL[mt][3]);
            }
            #pragma unroll
            for (int nh=0; nh<2; nh++){
                uint32_t bH[4][2], bL[4][2];
                #pragma unroll
                for (int np=0; np<2; np++){
                    int ntp = nh*2 + np;
                    uint32_t bd = sb + 2*PLANE + boff + (uint32_t)ntp*1024;
                    ldsm4(bd, bH[2*np][0], bH[2*np][1], bH[2*np+1][0], bH[2*np+1][1]);
                    ldsm4(bd + PLANE, bL[2*np][0], bL[2*np][1], bL[2*np+1][0], bL[2*np+1][1]);
                }
                #pragma unroll
                for (int mt=0; mt<2; mt++)
                    #pragma unroll
                    for (int nt=0; nt<4; nt++)
                        mma16816(acc[mt][nh*4+nt], aH[mt], bH[nt]);
                #pragma unroll
                for (int mt=0; mt<2; mt++)
                    #pragma unroll
                    for (int nt=0; nt<4; nt++)
                        mma16816(acc[mt][nh*4+nt], aH[mt], bL[nt]);
                #pragma unroll
                for (int mt=0; mt<2; mt++)
                    #pragma unroll
                    for (int nt=0; nt<4; nt++)
                        mma16816(acc[mt][nh*4+nt], aL[mt], bH[nt]);
            }
        }
        cur = (cur == 2) ? 0 : cur+1;
        nxt2 = (nxt2 == 2) ? 0 : nxt2+1;
    }

    const int rbase = bm + wm*32 + (lane>>2);
    const int cbase = bn + wn*64 + (lane&3)*2;

    if (EPI == EPI_QKV){
        const bool isqk = (bn < 2*Dc);
        #pragma unroll
        for (int mt=0; mt<2; mt++){
            #pragma unroll
            for (int half=0; half<2; half++){
                const int row = rbase + mt*16 + half*8;
                float vx[8], vy[8];
                float ss = 0.f;
                #pragma unroll
                for (int nt=0; nt<8; nt++){
                    const int col = cbase + nt*8;
                    float2 sc = *(const float2*)&aux[col];
                    float x = acc[mt][nt][half*2+0]*sc.x;
                    float y = acc[mt][nt][half*2+1]*sc.y;
                    vx[nt] = x; vy[nt] = y;
                    ss += x*x + y*y;
                }
                if (isqk){
                    ss += __shfl_xor_sync(0xffffffffu, ss, 1);
                    ss += __shfl_xor_sync(0xffffffffu, ss, 2);
                    float inv = 1.f / fmaxf(sqrtf(ss), 1e-5f);
                    #pragma unroll
                    for (int nt=0; nt<8; nt++){ vx[nt]*=inv; vy[nt]*=inv; }
                }
                #pragma unroll
                for (int nt=0; nt<8; nt++){
                    const int col = cbase + nt*8;
                    split2(vx[nt], vy[nt], Oh, Ol, (size_t)row*N + col);
                }
            }
        }
    } else {
        #pragma unroll
        for (int mt=0; mt<2; mt++){
            #pragma unroll
            for (int nt=0; nt<8; nt++){
                const int col = cbase + nt*8;
                #pragma unroll
                for (int half=0; half<2; half++){
                    const int row = rbase + mt*16 + half*8;
                    float vxx = acc[mt][nt][half*2+0];
                    float vyy = acc[mt][nt][half*2+1];
                    if (EPI == EPI_ADD){
                        float2 r = *(const float2*)&aux[(size_t)row*N + col];
                        vxx += r.x; vyy += r.y;
                        *(float2*)&C[(size_t)row*N + col] = make_float2(vxx, vyy);
                        split2(vxx, vyy, Oh, Ol, (size_t)row*N + col);
                    } else {
                        vxx = gelu_exact(vxx); vyy = gelu_exact(vyy);
                        split2(vxx, vyy, Oh, Ol, (size_t)row*N + col);
                    }
                }
            }
        }
    }
}

// ---------------- HMMA flash attention: BM=128, BN=64, SW128 swizzle,
//  S = Qh.Kh (1 product); PV = pH.Vh (1 product); both drops error-calibrated ---
#define APL 8192                   // 64 rows x 128B swizzled
#define ASTG (2*APL)               // 16384  (Kh, Vh)
#define NATT 4
#define ATT_SMEM (NATT*ASTG)       // 65536

__device__ __forceinline__ void attn_load(uint32_t s0, int b, int h, int kbase){
    const int tid = threadIdx.x;
    #pragma unroll
    for (int t=0; t<4; t++){
        int id = t*256 + tid;          // 0..1023
        int plane = id >> 9;           // 0=Kh, 1=Vh
        int rem = id & 511;
        int row = rem >> 3, c = rem & 7;
        uint32_t dst = s0 + plane*APL + row*128 + 16*(c ^ (row & 7));
        const __nv_bfloat16* src = g_qkvH + (size_t)(b*Tc + kbase + row)*(3*Dc)
                                 + ((plane == 0) ? Dc : 2*Dc) + h*HDc + c*8;
        cpasync16(dst, src);
    }
}

__global__ __launch_bounds__(256)
void attn_mma(){
    extern __shared__ char smc[];
    const uint32_t sb = smem_u32(smc);
    const int tid = threadIdx.x;
    const int wid = tid >> 5, lane = tid & 31;
    const int qt = (int)gridDim.x - 1 - (int)blockIdx.x;     // heavy CTAs first
    const int bh = blockIdx.y, b = bh >> 4, h = bh & 15;
    const int qbase = qt*128;
    const int wrow = qbase + wid*16;
    const int cq = (lane & 3)*2;
    const int r1g = wrow + (lane >> 2), r2g = r1g + 8;

    uint32_t aQh[4][4];
    {
        const size_t rb1 = (size_t)(b*Tc + r1g)*(3*Dc) + h*HDc;
        const size_t rb2 = (size_t)(b*Tc + r2g)*(3*Dc) + h*HDc;
        #pragma unroll
        for (int c=0;c<4;c++){
            int col = 16*c + cq;
            aQh[c][0] = *(const uint32_t*)&g_qkvH[rb1 + col];
            aQh[c][1] = *(const uint32_t*)&g_qkvH[rb2 + col];
            aQh[c][2] = *(const uint32_t*)&g_qkvH[rb1 + col + 8];
            aQh[c][3] = *(const uint32_t*)&g_qkvH[rb2 + col + 8];
        }
    }

    float O[8][4];
    #pragma unroll
    for (int j=0;j<8;j++){ O[j][0]=0.f; O[j][1]=0.f; O[j][2]=0.f; O[j][3]=0.f; }
    float m1=-1e30f, m2=-1e30f, l1=0.f, l2=0.f;

    const uint32_t brow = (uint32_t)(((lane>>4)<<3) + (lane & 7));
    const uint32_t bbit = (uint32_t)((lane>>3) & 1);
    const uint32_t bsw  = (uint32_t)(lane & 7);
    const uint32_t vrow_l = (uint32_t)((lane & 7) + (((lane>>3)&1) << 3));
    const uint32_t vchk_l = (uint32_t)(lane >> 4);
    const int nkt = 2*qt + 2;

    attn_load(sb + 0*ASTG, b, h, 0);
    CP_COMMIT();
    attn_load(sb + 1*ASTG, b, h, 64);
    CP_COMMIT();
    if (nkt > 2) attn_load(sb + 2*ASTG, b, h, 128);
    CP_COMMIT();

    for (int kt=0; kt<nkt; kt++){
        CP_WAIT2();
        __syncthreads();
        if (kt+3 < nkt)
            attn_load(sb + ((kt+3)&3)*ASTG, b, h, (kt+3)*64);
        CP_COMMIT();    // always commit -> wait_group 2 stays exact

        const uint32_t st = sb + (kt&3)*ASTG;
        const int kbase = kt*64;

        // ---- S = Qh Kh^T (1 product) ----
        float S[8][4];
        #pragma unroll
        for (int j=0;j<8;j++){ S[j][0]=0.f; S[j][1]=0.f; S[j][2]=0.f; S[j][3]=0.f; }
        #pragma unroll
        for (int c=0;c<4;c++){
            const uint32_t coff = 16u*(((uint32_t)(2*c) | bbit) ^ bsw);
            uint32_t bKh[8][2];
            #pragma unroll
            for (int ntp=0; ntp<4; ntp++){
                uint32_t ad = st + (brow + (uint32_t)ntp*16)*128 + coff;
                ldsm4(ad, bKh[2*ntp][0], bKh[2*ntp][1], bKh[2*ntp+1][0], bKh[2*ntp+1][1]);
            }
            #pragma unroll
            for (int j=0;j<8;j++) mma16816(S[j], aQh[c], bKh[j]);
        }

        // ---- scale + mask ----
        const bool need_mask = (kt >= 2*qt);
        #pragma unroll
        for (int j=0;j<8;j++){
            int col0 = kbase + j*8 + cq;
            #pragma unroll
            for (int e=0;e<4;e++){
                float v = S[j][e]*0.125f;
                if (need_mask){
                    int col = col0 + (e & 1);
                    int row = (e < 2) ? r1g : r2g;
                    if (col > row) v = -1e30f;
                }
                S[j][e] = v;
            }
        }

        // ---- online softmax ----
        float mx1=-1e30f, mx2=-1e30f;
        #pragma unroll
        for (int j=0;j<8;j++){
            mx1 = fmaxf(mx1, fmaxf(S[j][0], S[j][1]));
            mx2 = fmaxf(mx2, fmaxf(S[j][2], S[j][3]));
        }
        #pragma unroll
        for (int o=1;o<4;o<<=1){
            mx1 = fmaxf(mx1, __shfl_xor_sync(0xffffffffu, mx1, o));
            mx2 = fmaxf(mx2, __shfl_xor_sync(0xffffffffu, mx2, o));
        }
        float mn1 = fmaxf(m1, mx1), mn2 = fmaxf(m2, mx2);
        float co1 = __expf(m1 - mn1), co2 = __expf(m2 - mn2);
        float rs1 = 0.f, rs2 = 0.f;
        #pragma unroll
        for (int j=0;j<8;j++){
            S[j][0] = __expf(S[j][0]-mn1); S[j][1] = __expf(S[j][1]-mn1);
            S[j][2] = __expf(S[j][2]-mn2); S[j][3] = __expf(S[j][3]-mn2);
            rs1 += S[j][0] + S[j][1];
            rs2 += S[j][2] + S[j][3];
        }
        #pragma unroll
        for (int o=1;o<4;o<<=1){
            rs1 += __shfl_xor_sync(0xffffffffu, rs1, o);
            rs2 += __shfl_xor_sync(0xffffffffu, rs2, o);
        }
        l1 = l1*co1 + rs1;  m1 = mn1;
        l2 = l2*co2 + rs2;  m2 = mn2;
        #pragma unroll
        for (int j=0;j<8;j++){
            O[j][0]*=co1; O[j][1]*=co1; O[j][2]*=co2; O[j][3]*=co2;
        }

        // ---- pack P into A-fragments (hi only) ----
        uint32_t pH[4][4];
        #pragma unroll
        for (int c=0;c<4;c++){
            pH[c][0] = pack2(S[2*c][0],   S[2*c][1]);
            pH[c][1] = pack2(S[2*c][2],   S[2*c][3]);
            pH[c][2] = pack2(S[2*c+1][0], S[2*c+1][1]);
            pH[c][3] = pack2(S[2*c+1][2], S[2*c+1][3]);
        }

        // ---- O += pH Vh (1 product); V natural layout, trans ldmatrix ----
        #pragma unroll
        for (int c=0;c<4;c++){
            const uint32_t vrow = (uint32_t)(c*16) + vrow_l;
            uint32_t bVh[8][2];
            #pragma unroll
            for (int ntp=0; ntp<4; ntp++){
                uint32_t chunk = ((uint32_t)(2*ntp) + vchk_l) ^ (vrow & 7);
                uint32_t ad = st + APL + vrow*128 + 16u*chunk;
                ldsm4t(ad, bVh[2*ntp][0], bVh[2*ntp][1], bVh[2*ntp+1][0], bVh[2*ntp+1][1]);
            }
            #pragma unroll
            for (int j=0;j<8;j++) mma16816(O[j], pH[c], bVh[j]);
        }
    }

    const float i1 = 1.f/l1, i2 = 1.f/l2;
    const size_t ob1 = (size_t)(b*Tc + r1g)*Dc + h*HDc;
    const size_t ob2 = (size_t)(b*Tc + r2g)*Dc + h*HDc;
    #pragma unroll
    for (int j=0;j<8;j++){
        int col = j*8 + cq;
        split2(O[j][0]*i1, O[j][1]*i1, g_aH, g_aL, ob1 + col);
        split2(O[j][2]*i2, O[j][3]*i2, g_aH, g_aL, ob2 + col);
    }
}

// ---------------- final LayerNorm ----------------
__global__ void ln_kernel(const float* __restrict__ gamma, float* __restrict__ out){
    const int row = blockIdx.x, t = threadIdx.x;
    const float* x = g_x + (size_t)row*Dc;
    float4 xv = ((const float4*)x)[t];
    float s = xv.x+xv.y+xv.z+xv.w;
    __shared__ float red[16];
    #pragma unroll
    for (int o=16;o;o>>=1) s += __shfl_xor_sync(0xffffffffu, s, o);
    if ((t&31)==0) red[t>>5] = s;
    __syncthreads();
    float tot = 0.f;
    #pragma unroll
    for (int w=0;w<8;w++) tot += red[w];
    float mean = tot*(1.f/Dc);
    float dx=xv.x-mean, dy=xv.y-mean, dz=xv.z-mean, dw=xv.w-mean;
    float ss = dx*dx+dy*dy+dz*dz+dw*dw;
    #pragma unroll
    for (int o=16;o;o>>=1) ss += __shfl_xor_sync(0xffffffffu, ss, o);
    if ((t&31)==0) red[8+(t>>5)] = ss;
    __syncthreads();
    float tv = 0.f;
    #pragma unroll
    for (int w=0;w<8;w++) tv += red[8+w];
    float inv = rsqrtf(tv*(1.f/Dc) + 1e-5f);
    float4 g4 = ((const float4*)gamma)[t];
    float4 o4 = make_float4(dx*inv*g4.x, dy*inv*g4.y, dz*inv*g4.z, dw*inv*g4.w);
    ((float4*)out)[(size_t)row*(Dc/4) + t] = o4;
}

// ---------------- launch ----------------
extern "C" void kernel_launch(void* const* d_in, const int* in_sizes, int n_in,
                              void* d_out, int out_size)
{
    const float* q      = (const float*)d_in[0];
    const float* pos    = (const float*)d_in[1];
    const float* Wqkv   = (const float*)d_in[2];
    const float* convw  = (const float*)d_in[3];
    const float* projw  = (const float*)d_in[4];
    const float* fcw    = (const float*)d_in[5];
    const float* mlpw   = (const float*)d_in[6];
    const float* gamma  = (const float*)d_in[7];

    float *px;
    cudaGetSymbolAddress((void**)&px, g_x);
    __nv_bfloat16 *xH,*xL,*aH,*aL,*qkvH,*qkvL,*wqkvH,*wqkvL,*projH,*projL,*fcH,*fcL,*mlpH,*mlpL;
    cudaGetSymbolAddress((void**)&xH, g_xH);   cudaGetSymbolAddress((void**)&xL, g_xL);
    cudaGetSymbolAddress((void**)&aH, g_aH);   cudaGetSymbolAddress((void**)&aL, g_aL);
    cudaGetSymbolAddress((void**)&qkvH, g_qkvH); cudaGetSymbolAddress((void**)&qkvL, g_qkvL);
    cudaGetSymbolAddress((void**)&wqkvH, g_wqkvH); cudaGetSymbolAddress((void**)&wqkvL, g_wqkvL);
    cudaGetSymbolAddress((void**)&projH, g_projH); cudaGetSymbolAddress((void**)&projL, g_projL);
    cudaGetSymbolAddress((void**)&fcH, g_fcH);     cudaGetSymbolAddress((void**)&fcL, g_fcL);
    cudaGetSymbolAddress((void**)&mlpH, g_mlpH);   cudaGetSymbolAddress((void**)&mlpL, g_mlpL);

    cudaFuncSetAttribute(attn_mma, cudaFuncAttributeMaxDynamicSharedMemorySize, ATT_SMEM);
    cudaFuncSetAttribute(gemm_mma<EPI_QKV>,  cudaFuncAttributeMaxDynamicSharedMemorySize, GEMM_SMEM);
    cudaFuncSetAttribute(gemm_mma<EPI_ADD>,  cudaFuncAttributeMaxDynamicSharedMemorySize, GEMM_SMEM);
    cudaFuncSetAttribute(gemm_mma<EPI_GELU>, cudaFuncAttributeMaxDynamicSharedMemorySize, GEMM_SMEM);

    // split weights
    {
        int n4;
        n4 = Lc*3*Dc*Dc/4; split_kernel<<<n4/256, 256>>>(Wqkv, wqkvH, wqkvL, n4);
        n4 = Lc*Dc*Dc/4;   split_kernel<<<n4/256, 256>>>(projw, projH, projL, n4);
        n4 = Lc*FFc*Dc/4;  split_kernel<<<n4/256, 256>>>(fcw, fcH, fcL, n4);
        n4 = Lc*Dc*FFc/4;  split_kernel<<<n4/256, 256>>>(mlpw, mlpH, mlpL, n4);
    }

    posadd_kernel<<<Mc*Dc/4/256, 256>>>(q, pos);

    for (int l=0; l<Lc; l++){
        gemm_mma<EPI_QKV><<<dim3(3*Dc/128, Mc/128), 256, GEMM_SMEM>>>(
            xH, xL, wqkvH + (size_t)l*3*Dc*Dc, wqkvL + (size_t)l*3*Dc*Dc,
            convw + (size_t)l*3*Dc, nullptr, qkvH, qkvL, 3*Dc, Dc);
        attn_mma<<<dim3(Tc/128, Bc*Hc), 256, ATT_SMEM>>>();
        gemm_mma<EPI_ADD><<<dim3(Dc/128, Mc/128), 256, GEMM_SMEM>>>(
            aH, aL, projH + (size_t)l*Dc*Dc, projL + (size_t)l*Dc*Dc,
            px, px, xH, xL, Dc, Dc);
        gemm_mma<EPI_GELU><<<dim3(FFc/128, Mc/128), 256, GEMM_SMEM>>>(
            xH, xL, fcH + (size_t)l*FFc*Dc, fcL + (size_t)l*FFc*Dc,
            nullptr, nullptr, aH, aL, FFc, Dc);
        gemm_mma<EPI_ADD><<<dim3(Dc/128, Mc/128), 256, GEMM_SMEM>>>(
            aH, aL, mlpH + (size_t)l*Dc*FFc, mlpL + (size_t)l*Dc*FFc,
            px, px, xH, xL, Dc, FFc);
    }

    ln_kernel<<<Mc, 256>>>(gamma, (float*)d_out);
}

// round 17
// speedup vs baseline: 1.1679x; 1.0537x over previous
#include <cuda_runtime.h>
#include <cuda_bf16.h>
#include <math.h>
#include <stdint.h>

// Problem dims
#define Lc 8
#define Dc 1024
#define Hc 16
#define FFc 4096
#define Tc 2048
#define Bc 2
#define HDc 64
#define Mc (Bc*Tc)   // 4096 tokens

// ---------------- scratch (device globals) ----------------
__device__ float g_x[Mc*Dc];

__device__ __nv_bfloat16 g_xH[(size_t)Mc*Dc];
__device__ __nv_bfloat16 g_xL[(size_t)Mc*Dc];
__device__ __nv_bfloat16 g_aH[(size_t)Mc*FFc];
__device__ __nv_bfloat16 g_aL[(size_t)Mc*FFc];
__device__ __nv_bfloat16 g_qkvH[(size_t)Mc*3*Dc];   // q,k normalized; v scaled
__device__ __nv_bfloat16 g_qkvL[(size_t)Mc*3*Dc];
__device__ __nv_bfloat16 g_wqkvH[(size_t)Lc*3*Dc*Dc];   // hi-only (2-product GEMM)
__device__ __nv_bfloat16 g_projH[(size_t)Lc*Dc*Dc];
__device__ __nv_bfloat16 g_projL[(size_t)Lc*Dc*Dc];
__device__ __nv_bfloat16 g_fcH[(size_t)Lc*FFc*Dc];
__device__ __nv_bfloat16 g_fcL[(size_t)Lc*FFc*Dc];
__device__ __nv_bfloat16 g_mlpH[(size_t)Lc*Dc*FFc];
__device__ __nv_bfloat16 g_mlpL[(size_t)Lc*Dc*FFc];

__device__ __forceinline__ float gelu_exact(float v){
    return 0.5f*v*(1.0f + erff(v*0.70710678118654752f));
}

// ---------------- PTX helpers ----------------
__device__ __forceinline__ uint32_t smem_u32(const void* p){
    uint32_t a;
    asm("{ .reg .u64 t; cvta.to.shared.u64 t, %1; cvt.u32.u64 %0, t; }" : "=r"(a) : "l"(p));
    return a;
}
#define CP_COMMIT()  asm volatile("cp.async.commit_group;" ::: "memory")
#define CP_WAIT1()   asm volatile("cp.async.wait_group 1;" ::: "memory")
#define CP_WAIT2()   asm volatile("cp.async.wait_group 2;" ::: "memory")
#define CP_WAIT0()   asm volatile("cp.async.wait_group 0;" ::: "memory")

__device__ __forceinline__ void cpasync16(uint32_t dst, const void* src){
    asm volatile("cp.async.cg.shared.global [%0], [%1], 16;" :: "r"(dst), "l"(src));
}
__device__ __forceinline__ void ldsm4(uint32_t addr, uint32_t& r0, uint32_t& r1, uint32_t& r2, uint32_t& r3){
    asm volatile("ldmatrix.sync.aligned.m8n8.x4.shared.b16 {%0,%1,%2,%3}, [%4];"
        : "=r"(r0), "=r"(r1), "=r"(r2), "=r"(r3) : "r"(addr));
}
__device__ __forceinline__ void ldsm4t(uint32_t addr, uint32_t& r0, uint32_t& r1, uint32_t& r2, uint32_t& r3){
    asm volatile("ldmatrix.sync.aligned.m8n8.x4.trans.shared.b16 {%0,%1,%2,%3}, [%4];"
        : "=r"(r0), "=r"(r1), "=r"(r2), "=r"(r3) : "r"(addr));
}
__device__ __forceinline__ void mma16816(float* c, const uint32_t* a, const uint32_t* b){
    asm volatile("mma.sync.aligned.m16n8k16.row.col.f32.bf16.bf16.f32 "
        "{%0,%1,%2,%3}, {%4,%5,%6,%7}, {%8,%9}, {%0,%1,%2,%3};"
        : "+f"(c[0]), "+f"(c[1]), "+f"(c[2]), "+f"(c[3])
        : "r"(a[0]), "r"(a[1]), "r"(a[2]), "r"(a[3]), "r"(b[0]), "r"(b[1]));
}

// ---------------- split helpers ----------------
__device__ __forceinline__ void split4(float4 v, __nv_bfloat16* hi, __nv_bfloat16* lo, size_t e){
    __nv_bfloat16 h0=__float2bfloat16(v.x), h1=__float2bfloat16(v.y);
    __nv_bfloat16 h2=__float2bfloat16(v.z), h3=__float2bfloat16(v.w);
    __nv_bfloat16 l0=__float2bfloat16(v.x-__bfloat162float(h0));
    __nv_bfloat16 l1=__float2bfloat16(v.y-__bfloat162float(h1));
    __nv_bfloat16 l2=__float2bfloat16(v.z-__bfloat162float(h2));
    __nv_bfloat16 l3=__float2bfloat16(v.w-__bfloat162float(h3));
    __nv_bfloat162 hp0; hp0.x=h0; hp0.y=h1;
    __nv_bfloat162 hp1; hp1.x=h2; hp1.y=h3;
    __nv_bfloat162 lp0; lp0.x=l0; lp0.y=l1;
    __nv_bfloat162 lp1; lp1.x=l2; lp1.y=l3;
    ((__nv_bfloat162*)hi)[e/2]   = hp0;
    ((__nv_bfloat162*)hi)[e/2+1] = hp1;
    ((__nv_bfloat162*)lo)[e/2]   = lp0;
    ((__nv_bfloat162*)lo)[e/2+1] = lp1;
}
__device__ __forceinline__ void split2(float x, float y, __nv_bfloat16* hi, __nv_bfloat16* lo, size_t e){
    __nv_bfloat16 h0=__float2bfloat16(x), h1=__float2bfloat16(y);
    __nv_bfloat16 l0=__float2bfloat16(x-__bfloat162float(h0));
    __nv_bfloat16 l1=__float2bfloat16(y-__bfloat162float(h1));
    __nv_bfloat162 hp; hp.x=h0; hp.y=h1;
    __nv_bfloat162 lp; lp.x=l0; lp.y=l1;
    ((__nv_bfloat162*)hi)[e/2] = hp;
    ((__nv_bfloat162*)lo)[e/2] = lp;
}
__device__ __forceinline__ uint32_t pack2(float x, float y){
    __nv_bfloat162 hp; hp.x=__float2bfloat16(x); hp.y=__float2bfloat16(y);
    return *(uint32_t*)&hp;
}

__global__ void split_kernel(const float* __restrict__ s, __nv_bfloat16* __restrict__ hi,
                             __nv_bfloat16* __restrict__ lo, int n4){
    int i = blockIdx.x*blockDim.x + threadIdx.x;
    if (i < n4){
        float4 v = ((const float4*)s)[i];
        split4(v, hi, lo, (size_t)i*4);
    }
}

// hi-only convert (for weights whose lo plane is dropped)
__global__ void convhi_kernel(const float* __restrict__ s, __nv_bfloat16* __restrict__ hi, int n4){
    int i = blockIdx.x*blockDim.x + threadIdx.x;
    if (i < n4){
        float4 v = ((const float4*)s)[i];
        __nv_bfloat162 hp0; hp0.x=__float2bfloat16(v.x); hp0.y=__float2bfloat16(v.y);
        __nv_bfloat162 hp1; hp1.x=__float2bfloat16(v.z); hp1.y=__float2bfloat16(v.w);
        ((__nv_bfloat162*)hi)[(size_t)i*2]   = hp0;
        ((__nv_bfloat162*)hi)[(size_t)i*2+1] = hp1;
    }
}

// ---------------- pos add ----------------
__global__ void posadd_kernel(const float* __restrict__ q, const float* __restrict__ pos){
    int idx = blockIdx.x*blockDim.x + threadIdx.x;
    const int n4 = Mc*Dc/4;
    if (idx < n4){
        float4 a = ((const float4*)q)[idx];
        int pidx = idx % (Tc*Dc/4);
        float4 p = ((const float4*)pos)[pidx];
        a.x+=p.x; a.y+=p.y; a.z+=p.z; a.w+=p.w;
        ((float4*)g_x)[idx] = a;
        split4(a, g_xH, g_xL, (size_t)idx*4);
    }
}

// ---------------- HMMA GEMM; DROPBL=true -> 2-product (Ah.Bh + Al.Bh) --------
enum { EPI_QKV=0, EPI_ADD=1, EPI_GELU=2 };

#define PLANE 8192                 // 128 rows x 64B (swizzled)
#define STG   (4*PLANE)            // 32768
#define NSTAGE 3
#define GEMM_SMEM (NSTAGE*STG)     // 98304

template<bool DROPBL>
__device__ __forceinline__ void load_stage(uint32_t sb,
    const __nv_bfloat16* __restrict__ pAh, const __nv_bfloat16* __restrict__ pAl,
    const __nv_bfloat16* __restrict__ pBh, const __nv_bfloat16* __restrict__ pBl,
    int K, int kb)
{
    const __nv_bfloat16* planes[4] = {pAh, pAl, pBh, pBl};
    const int tid = threadIdx.x;
    const int NCH = DROPBL ? 6 : 8;     // plane order Ah,Al,Bh,Bl -> dropping tail
    #pragma unroll
    for (int t=0; t<NCH; t++){
        int id = t*256 + tid;
        int plane = id >> 9;
        int rem = id & 511;
        int row = rem >> 2, c = rem & 3;
        uint32_t dst = sb + plane*PLANE + row*64 + 16*(c ^ ((row>>1)&3));
        cpasync16(dst, planes[plane] + (size_t)row*K + kb*32 + c*8);
    }
}

template<int EPI, bool DROPBL>
__global__ __launch_bounds__(256,2)
void gemm_mma(const __nv_bfloat16* __restrict__ Ah, const __nv_bfloat16* __restrict__ Al,
              const __nv_bfloat16* __restrict__ Bh, const __nv_bfloat16* __restrict__ Bl,
              const float* __restrict__ aux, float* __restrict__ C,
              __nv_bfloat16* __restrict__ Oh, __nv_bfloat16* __restrict__ Ol,
              int N, int K)
{
    extern __shared__ char smem[];
    const uint32_t sbase = smem_u32(smem);
    const int tid = threadIdx.x;
    const int wid = tid >> 5, lane = tid & 31;
    const int wm = wid >> 1, wn = wid & 1;
    const int bm = blockIdx.y*128, bn = blockIdx.x*128;
    const int KB = K >> 5;

    const __nv_bfloat16* pAh = Ah + (size_t)bm*K;
    const __nv_bfloat16* pAl = Al + (size_t)bm*K;
    const __nv_bfloat16* pBh = Bh + (size_t)bn*K;
    const __nv_bfloat16* pBl = DROPBL ? Bh : (Bl + (size_t)bn*K);

    float acc[2][8][4];
    #pragma unroll
    for (int i=0;i<2;i++)
        #pragma unroll
        for (int j=0;j<8;j++)
            #pragma unroll
            for (int k=0;k<4;k++) acc[i][j][k]=0.f;

    const uint32_t s_lane = (lane >> 1) & 3;
    const uint32_t rowA = (uint32_t)(wm*32 + (lane & 15));
    const uint32_t aoff0 = rowA*64 + 16u*(((0u) | (uint32_t)(lane>>4)) ^ s_lane);
    const uint32_t aoff1 = rowA*64 + 16u*(((2u) | (uint32_t)(lane>>4)) ^ s_lane);
    const uint32_t rowB = (uint32_t)(wn*64 + ((lane>>4)<<3) + (lane & 7));
    const uint32_t bbit = (uint32_t)((lane>>3) & 1);
    const uint32_t boff0 = rowB*64 + 16u*(((0u) | bbit) ^ s_lane);
    const uint32_t boff1 = rowB*64 + 16u*(((2u) | bbit) ^ s_lane);

    load_stage<DROPBL>(sbase + 0*STG, pAh, pAl, pBh, pBl, K, 0);
    CP_COMMIT();
    load_stage<DROPBL>(sbase + 1*STG, pAh, pAl, pBh, pBl, K, 1);
    CP_COMMIT();

    int cur = 0, nxt2 = 2;
    for (int kb=0; kb<KB; kb++){
        if (kb+1 < KB) CP_WAIT1(); else CP_WAIT0();
        __syncthreads();
        if (kb+2 < KB){
            load_stage<DROPBL>(sbase + nxt2*STG, pAh, pAl, pBh, pBl, K, kb+2);
            CP_COMMIT();
        }

        const uint32_t sb = sbase + cur*STG;
        #pragma unroll
        for (int ks=0; ks<2; ks++){
            const uint32_t aoff = ks ? aoff1 : aoff0;
            const uint32_t boff = ks ? boff1 : boff0;
            uint32_t aH[2][4], aL[2][4];
            #pragma unroll
            for (int mt=0; mt<2; mt++){
                uint32_t ad = sb + aoff + (uint32_t)mt*1024;
                ldsm4(ad, aH[mt][0], aH[mt][1], aH[mt][2], aH[mt][3]);
                ldsm4(ad + PLANE, aL[mt][0], aL[mt][1], aL[mt][2], aL[mt][3]);
            }
            #pragma unroll
            for (int nh=0; nh<2; nh++){
                uint32_t bH[4][2];
                uint32_t bL[4][2];
                #pragma unroll
                for (int np=0; np<2; np++){
                    int ntp = nh*2 + np;
                    uint32_t bd = sb + 2*PLANE + boff + (uint32_t)ntp*1024;
                    ldsm4(bd, bH[2*np][0], bH[2*np][1], bH[2*np+1][0], bH[2*np+1][1]);
                    if (!DROPBL){
                        ldsm4(bd + PLANE, bL[2*np][0], bL[2*np][1], bL[2*np+1][0], bL[2*np+1][1]);
                    }
                }
                #pragma unroll
                for (int mt=0; mt<2; mt++)
                    #pragma unroll
                    for (int nt=0; nt<4; nt++)
                        mma16816(acc[mt][nh*4+nt], aH[mt], bH[nt]);
                if (!DROPBL){
                    #pragma unroll
                    for (int mt=0; mt<2; mt++)
                        #pragma unroll
                        for (int nt=0; nt<4; nt++)
                            mma16816(acc[mt][nh*4+nt], aH[mt], bL[nt]);
                }
                #pragma unroll
                for (int mt=0; mt<2; mt++)
                    #pragma unroll
                    for (int nt=0; nt<4; nt++)
                        mma16816(acc[mt][nh*4+nt], aL[mt], bH[nt]);
            }
        }
        cur = (cur == 2) ? 0 : cur+1;
        nxt2 = (nxt2 == 2) ? 0 : nxt2+1;
    }

    const int rbase = bm + wm*32 + (lane>>2);
    const int cbase = bn + wn*64 + (lane&3)*2;

    if (EPI == EPI_QKV){
        const bool isqk = (bn < 2*Dc);
        #pragma unroll
        for (int mt=0; mt<2; mt++){
            #pragma unroll
            for (int half=0; half<2; half++){
                const int row = rbase + mt*16 + half*8;
                float vx[8], vy[8];
                float ss = 0.f;
                #pragma unroll
                for (int nt=0; nt<8; nt++){
                    const int col = cbase + nt*8;
                    float2 sc = *(const float2*)&aux[col];
                    float x = acc[mt][nt][half*2+0]*sc.x;
                    float y = acc[mt][nt][half*2+1]*sc.y;
                    vx[nt] = x; vy[nt] = y;
                    ss += x*x + y*y;
                }
                if (isqk){
                    ss += __shfl_xor_sync(0xffffffffu, ss, 1);
                    ss += __shfl_xor_sync(0xffffffffu, ss, 2);
                    float inv = 1.f / fmaxf(sqrtf(ss), 1e-5f);
                    #pragma unroll
                    for (int nt=0; nt<8; nt++){ vx[nt]*=inv; vy[nt]*=inv; }
                }
                #pragma unroll
                for (int nt=0; nt<8; nt++){
                    const int col = cbase + nt*8;
                    split2(vx[nt], vy[nt], Oh, Ol, (size_t)row*N + col);
                }
            }
        }
    } else {
        #pragma unroll
        for (int mt=0; mt<2; mt++){
            #pragma unroll
            for (int nt=0; nt<8; nt++){
                const int col = cbase + nt*8;
                #pragma unroll
                for (int half=0; half<2; half++){
                    const int row = rbase + mt*16 + half*8;
                    float vxx = acc[mt][nt][half*2+0];
                    float vyy = acc[mt][nt][half*2+1];
                    if (EPI == EPI_ADD){
                        float2 r = *(const float2*)&aux[(size_t)row*N + col];
                        vxx += r.x; vyy += r.y;
                        *(float2*)&C[(size_t)row*N + col] = make_float2(vxx, vyy);
                        split2(vxx, vyy, Oh, Ol, (size_t)row*N + col);
                    } else {
                        vxx = gelu_exact(vxx); vyy = gelu_exact(vyy);
                        split2(vxx, vyy, Oh, Ol, (size_t)row*N + col);
                    }
                }
            }
        }
    }
}

// ---------------- HMMA flash attention (round-15 winner, unchanged) ----------
#define APL 8192                   // 64 rows x 128B swizzled
#define ASTG (2*APL)               // 16384  (Kh, Vh)
#define NATT 4
#define ATT_SMEM (NATT*ASTG)       // 65536

__device__ __forceinline__ void attn_load(uint32_t s0, int b, int h, int kbase){
    const int tid = threadIdx.x;
    #pragma unroll
    for (int t=0; t<4; t++){
        int id = t*256 + tid;
        int plane = id >> 9;           // 0=Kh, 1=Vh
        int rem = id & 511;
        int row = rem >> 3, c = rem & 7;
        uint32_t dst = s0 + plane*APL + row*128 + 16*(c ^ (row & 7));
        const __nv_bfloat16* src = g_qkvH + (size_t)(b*Tc + kbase + row)*(3*Dc)
                                 + ((plane == 0) ? Dc : 2*Dc) + h*HDc + c*8;
        cpasync16(dst, src);
    }
}

__global__ __launch_bounds__(256)
void attn_mma(){
    extern __shared__ char smc[];
    const uint32_t sb = smem_u32(smc);
    const int tid = threadIdx.x;
    const int wid = tid >> 5, lane = tid & 31;
    const int qt = (int)gridDim.x - 1 - (int)blockIdx.x;
    const int bh = blockIdx.y, b = bh >> 4, h = bh & 15;
    const int qbase = qt*128;
    const int wrow = qbase + wid*16;
    const int cq = (lane & 3)*2;
    const int r1g = wrow + (lane >> 2), r2g = r1g + 8;

    uint32_t aQh[4][4];
    {
        const size_t rb1 = (size_t)(b*Tc + r1g)*(3*Dc) + h*HDc;
        const size_t rb2 = (size_t)(b*Tc + r2g)*(3*Dc) + h*HDc;
        #pragma unroll
        for (int c=0;c<4;c++){
            int col = 16*c + cq;
            aQh[c][0] = *(const uint32_t*)&g_qkvH[rb1 + col];
            aQh[c][1] = *(const uint32_t*)&g_qkvH[rb2 + col];
            aQh[c][2] = *(const uint32_t*)&g_qkvH[rb1 + col + 8];
            aQh[c][3] = *(const uint32_t*)&g_qkvH[rb2 + col + 8];
        }
    }

    float O[8][4];
    #pragma unroll
    for (int j=0;j<8;j++){ O[j][0]=0.f; O[j][1]=0.f; O[j][2]=0.f; O[j][3]=0.f; }
    float m1=-1e30f, m2=-1e30f, l1=0.f, l2=0.f;

    const uint32_t brow = (uint32_t)(((lane>>4)<<3) + (lane & 7));
    const uint32_t bbit = (uint32_t)((lane>>3) & 1);
    const uint32_t bsw  = (uint32_t)(lane & 7);
    const uint32_t vrow_l = (uint32_t)((lane & 7) + (((lane>>3)&1) << 3));
    const uint32_t vchk_l = (uint32_t)(lane >> 4);
    const int nkt = 2*qt + 2;

    attn_load(sb + 0*ASTG, b, h, 0);
    CP_COMMIT();
    attn_load(sb + 1*ASTG, b, h, 64);
    CP_COMMIT();
    if (nkt > 2) attn_load(sb + 2*ASTG, b, h, 128);
    CP_COMMIT();

    for (int kt=0; kt<nkt; kt++){
        CP_WAIT2();
        __syncthreads();
        if (kt+3 < nkt)
            attn_load(sb + ((kt+3)&3)*ASTG, b, h, (kt+3)*64);
        CP_COMMIT();

        const uint32_t st = sb + (kt&3)*ASTG;
        const int kbase = kt*64;

        float S[8][4];
        #pragma unroll
        for (int j=0;j<8;j++){ S[j][0]=0.f; S[j][1]=0.f; S[j][2]=0.f; S[j][3]=0.f; }
        #pragma unroll
        for (int c=0;c<4;c++){
            const uint32_t coff = 16u*(((uint32_t)(2*c) | bbit) ^ bsw);
            uint32_t bKh[8][2];
            #pragma unroll
            for (int ntp=0; ntp<4; ntp++){
                uint32_t ad = st + (brow + (uint32_t)ntp*16)*128 + coff;
                ldsm4(ad, bKh[2*ntp][0], bKh[2*ntp][1], bKh[2*ntp+1][0], bKh[2*ntp+1][1]);
            }
            #pragma unroll
            for (int j=0;j<8;j++) mma16816(S[j], aQh[c], bKh[j]);
        }

        const bool need_mask = (kt >= 2*qt);
        #pragma unroll
        for (int j=0;j<8;j++){
            int col0 = kbase + j*8 + cq;
            #pragma unroll
            for (int e=0;e<4;e++){
                float v = S[j][e]*0.125f;
                if (need_mask){
                    int col = col0 + (e & 1);
                    int row = (e < 2) ? r1g : r2g;
                    if (col > row) v = -1e30f;
                }
                S[j][e] = v;
            }
        }

        float mx1=-1e30f, mx2=-1e30f;
        #pragma unroll
        for (int j=0;j<8;j++){
            mx1 = fmaxf(mx1, fmaxf(S[j][0], S[j][1]));
            mx2 = fmaxf(mx2, fmaxf(S[j][2], S[j][3]));
        }
        #pragma unroll
        for (int o=1;o<4;o<<=1){
            mx1 = fmaxf(mx1, __shfl_xor_sync(0xffffffffu, mx1, o));
            mx2 = fmaxf(mx2, __shfl_xor_sync(0xffffffffu, mx2, o));
        }
        float mn1 = fmaxf(m1, mx1), mn2 = fmaxf(m2, mx2);
        float co1 = __expf(m1 - mn1), co2 = __expf(m2 - mn2);
        float rs1 = 0.f, rs2 = 0.f;
        #pragma unroll
        for (int j=0;j<8;j++){
            S[j][0] = __expf(S[j][0]-mn1); S[j][1] = __expf(S[j][1]-mn1);
            S[j][2] = __expf(S[j][2]-mn2); S[j][3] = __expf(S[j][3]-mn2);
            rs1 += S[j][0] + S[j][1];
            rs2 += S[j][2] + S[j][3];
        }
        #pragma unroll
        for (int o=1;o<4;o<<=1){
            rs1 += __shfl_xor_sync(0xffffffffu, rs1, o);
            rs2 += __shfl_xor_sync(0xffffffffu, rs2, o);
        }
        l1 = l1*co1 + rs1;  m1 = mn1;
        l2 = l2*co2 + rs2;  m2 = mn2;
        #pragma unroll
        for (int j=0;j<8;j++){
            O[j][0]*=co1; O[j][1]*=co1; O[j][2]*=co2; O[j][3]*=co2;
        }

        uint32_t pH[4][4];
        #pragma unroll
        for (int c=0;c<4;c++){
            pH[c][0] = pack2(S[2*c][0],   S[2*c][1]);
            pH[c][1] = pack2(S[2*c][2],   S[2*c][3]);
            pH[c][2] = pack2(S[2*c+1][0], S[2*c+1][1]);
            pH[c][3] = pack2(S[2*c+1][2], S[2*c+1][3]);
        }

        #pragma unroll
        for (int c=0;c<4;c++){
            const uint32_t vrow = (uint32_t)(c*16) + vrow_l;
            uint32_t bVh[8][2];
            #pragma unroll
            for (int ntp=0; ntp<4; ntp++){
                uint32_t chunk = ((uint32_t)(2*ntp) + vchk_l) ^ (vrow & 7);
                uint32_t ad = st + APL + vrow*128 + 16u*chunk;
                ldsm4t(ad, bVh[2*ntp][0], bVh[2*ntp][1], bVh[2*ntp+1][0], bVh[2*ntp+1][1]);
            }
            #pragma unroll
            for (int j=0;j<8;j++) mma16816(O[j], pH[c], bVh[j]);
        }
    }

    const float i1 = 1.f/l1, i2 = 1.f/l2;
    const size_t ob1 = (size_t)(b*Tc + r1g)*Dc + h*HDc;
    const size_t ob2 = (size_t)(b*Tc + r2g)*Dc + h*HDc;
    #pragma unroll
    for (int j=0;j<8;j++){
        int col = j*8 + cq;
        split2(O[j][0]*i1, O[j][1]*i1, g_aH, g_aL, ob1 + col);
        split2(O[j][2]*i2, O[j][3]*i2, g_aH, g_aL, ob2 + col);
    }
}

// ---------------- final LayerNorm ----------------
__global__ void ln_kernel(const float* __restrict__ gamma, float* __restrict__ out){
    const int row = blockIdx.x, t = threadIdx.x;
    const float* x = g_x + (size_t)row*Dc;
    float4 xv = ((const float4*)x)[t];
    float s = xv.x+xv.y+xv.z+xv.w;
    __shared__ float red[16];
    #pragma unroll
    for (int o=16;o;o>>=1) s += __shfl_xor_sync(0xffffffffu, s, o);
    if ((t&31)==0) red[t>>5] = s;
    __syncthreads();
    float tot = 0.f;
    #pragma unroll
    for (int w=0;w<8;w++) tot += red[w];
    float mean = tot*(1.f/Dc);
    float dx=xv.x-mean, dy=xv.y-mean, dz=xv.z-mean, dw=xv.w-mean;
    float ss = dx*dx+dy*dy+dz*dz+dw*dw;
    #pragma unroll
    for (int o=16;o;o>>=1) ss += __shfl_xor_sync(0xffffffffu, ss, o);
    if ((t&31)==0) red[8+(t>>5)] = ss;
    __syncthreads();
    float tv = 0.f;
    #pragma unroll
    for (int w=0;w<8;w++) tv += red[8+w];
    float inv = rsqrtf(tv*(1.f/Dc) + 1e-5f);
    float4 g4 = ((const float4*)gamma)[t];
    float4 o4 = make_float4(dx*inv*g4.x, dy*inv*g4.y, dz*inv*g4.z, dw*inv*g4.w);
    ((float4*)out)[(size_t)row*(Dc/4) + t] = o4;
}

// ---------------- launch ----------------
extern "C" void kernel_launch(void* const* d_in, const int* in_sizes, int n_in,
                              void* d_out, int out_size)
{
    const float* q      = (const float*)d_in[0];
    const float* pos    = (const float*)d_in[1];
    const float* Wqkv   = (const float*)d_in[2];
    const float* convw  = (const float*)d_in[3];
    const float* projw  = (const float*)d_in[4];
    const float* fcw    = (const float*)d_in[5];
    const float* mlpw   = (const float*)d_in[6];
    const float* gamma  = (const float*)d_in[7];

    float *px;
    cudaGetSymbolAddress((void**)&px, g_x);
    __nv_bfloat16 *xH,*xL,*aH,*aL,*qkvH,*qkvL,*wqkvH,*projH,*projL,*fcH,*fcL,*mlpH,*mlpL;
    cudaGetSymbolAddress((void**)&xH, g_xH);   cudaGetSymbolAddress((void**)&xL, g_xL);
    cudaGetSymbolAddress((void**)&aH, g_aH);   cudaGetSymbolAddress((void**)&aL, g_aL);
    cudaGetSymbolAddress((void**)&qkvH, g_qkvH); cudaGetSymbolAddress((void**)&qkvL, g_qkvL);
    cudaGetSymbolAddress((void**)&wqkvH, g_wqkvH);
    cudaGetSymbolAddress((void**)&projH, g_projH); cudaGetSymbolAddress((void**)&projL, g_projL);
    cudaGetSymbolAddress((void**)&fcH, g_fcH);     cudaGetSymbolAddress((void**)&fcL, g_fcL);
    cudaGetSymbolAddress((void**)&mlpH, g_mlpH);   cudaGetSymbolAddress((void**)&mlpL, g_mlpL);

    cudaFuncSetAttribute(attn_mma, cudaFuncAttributeMaxDynamicSharedMemorySize, ATT_SMEM);
    cudaFuncSetAttribute(gemm_mma<EPI_QKV,true>,   cudaFuncAttributeMaxDynamicSharedMemorySize, GEMM_SMEM);
    cudaFuncSetAttribute(gemm_mma<EPI_ADD,false>,  cudaFuncAttributeMaxDynamicSharedMemorySize, GEMM_SMEM);
    cudaFuncSetAttribute(gemm_mma<EPI_GELU,false>, cudaFuncAttributeMaxDynamicSharedMemorySize, GEMM_SMEM);

    // weight conversion: QKV hi-only (2-product); proj/fc/mlp full split (3-product)
    {
        int n4;
        n4 = Lc*3*Dc*Dc/4; convhi_kernel<<<n4/256, 256>>>(Wqkv, wqkvH, n4);
        n4 = Lc*Dc*Dc/4;   split_kernel<<<n4/256, 256>>>(projw, projH, projL, n4);
        n4 = Lc*FFc*Dc/4;  split_kernel<<<n4/256, 256>>>(fcw, fcH, fcL, n4);
        n4 = Lc*Dc*FFc/4;  split_kernel<<<n4/256, 256>>>(mlpw, mlpH, mlpL, n4);
    }

    posadd_kernel<<<Mc*Dc/4/256, 256>>>(q, pos);

    for (int l=0; l<Lc; l++){
        // QKV: 2-product (q/k logit-protected; v error = calibrated Vl-class, +1.7e-4)
        gemm_mma<EPI_QKV,true><<<dim3(3*Dc/128, Mc/128), 256, GEMM_SMEM>>>(
            xH, xL, wqkvH + (size_t)l*3*Dc*Dc, nullptr,
            convw + (size_t)l*3*Dc, nullptr, qkvH, qkvL, 3*Dc, Dc);
        attn_mma<<<dim3(Tc/128, Bc*Hc), 256, ATT_SMEM>>>();
        // proj: 3-product
        gemm_mma<EPI_ADD,false><<<dim3(Dc/128, Mc/128), 256, GEMM_SMEM>>>(
            aH, aL, projH + (size_t)l*Dc*Dc, projL + (size_t)l*Dc*Dc,
            px, px, xH, xL, Dc, Dc);
        // fc: 3-product (round-16 showed its path has ~no dilution; keep full precision)
        gemm_mma<EPI_GELU,false><<<dim3(FFc/128, Mc/128), 256, GEMM_SMEM>>>(
            xH, xL, fcH + (size_t)l*FFc*Dc, fcL + (size_t)l*FFc*Dc,
            nullptr, nullptr, aH, aL, FFc, Dc);
        // mlp: 3-product
        gemm_mma<EPI_ADD,false><<<dim3(Dc/128, Mc/128), 256, GEMM_SMEM>>>(
            aH, aL, mlpH + (size_t)l*Dc*FFc, mlpL + (size_t)l*Dc*FFc,
            px, px, xH, xL, Dc, FFc);
    }

    ln_kernel<<<Mc, 256>>>(gamma, (float*)d_out);
}